// round 1
// baseline (speedup 1.0000x reference)
#include <cuda_runtime.h>
#include <math.h>

#define D_MODEL 512
#define N_HEADS 8
#define DK      64
#define D_FF    2048
#define BATCH   2
#define SEQ     2048
#define NTOK    (BATCH * SEQ)   // 4096

// ---------------- scratch (device globals; no allocation allowed) ----------
static __device__ float g_q  [(size_t)NTOK * D_MODEL];
static __device__ float g_k  [(size_t)NTOK * D_MODEL];
static __device__ float g_v  [(size_t)NTOK * D_MODEL];
static __device__ float g_ctx[(size_t)NTOK * D_MODEL];
static __device__ float g_x1 [(size_t)NTOK * D_MODEL];
static __device__ float g_tmp[(size_t)NTOK * D_MODEL];
static __device__ float g_ff [(size_t)NTOK * D_FF];

// ---------------- generic tiled SGEMM: C = A[MxK] @ B[KxN] + bias (+ReLU) --
template <bool RELU>
__launch_bounds__(256, 2)
__global__ void sgemm_bias_kernel(const float* __restrict__ A,
                                  const float* __restrict__ B,
                                  const float* __restrict__ bias,
                                  float* __restrict__ C,
                                  int M, int N, int K)
{
    constexpr int BM = 128, BN = 128, BK = 16;
    __shared__ float As[BK][BM];
    __shared__ float Bs[BK][BN];

    const int tid = threadIdx.x;
    const int bm  = blockIdx.y * BM;
    const int bn  = blockIdx.x * BN;
    const int tr  = (tid / 16) * 8;
    const int tc  = (tid % 16) * 8;

    float acc[8][8];
#pragma unroll
    for (int i = 0; i < 8; i++)
#pragma unroll
        for (int j = 0; j < 8; j++) acc[i][j] = 0.f;

    for (int k0 = 0; k0 < K; k0 += BK) {
        // load A tile (BM x BK), store transposed As[k][m]
#pragma unroll
        for (int t = 0; t < 2; t++) {
            int f = tid + t * 256;          // 512 float4 total
            int r = f >> 2, cv = (f & 3) * 4;
            float4 a4 = *(const float4*)(A + (size_t)(bm + r) * K + (k0 + cv));
            As[cv + 0][r] = a4.x;
            As[cv + 1][r] = a4.y;
            As[cv + 2][r] = a4.z;
            As[cv + 3][r] = a4.w;
        }
        // load B tile (BK x BN)
#pragma unroll
        for (int t = 0; t < 2; t++) {
            int f = tid + t * 256;
            int r = f >> 5, cv = (f & 31) * 4;
            *(float4*)(&Bs[r][cv]) =
                *(const float4*)(B + (size_t)(k0 + r) * N + (bn + cv));
        }
        __syncthreads();

#pragma unroll
        for (int kk = 0; kk < BK; kk++) {
            float a[8], b[8];
#pragma unroll
            for (int i = 0; i < 8; i++) a[i] = As[kk][tr + i];
#pragma unroll
            for (int j = 0; j < 8; j++) b[j] = Bs[kk][tc + j];
#pragma unroll
            for (int i = 0; i < 8; i++)
#pragma unroll
                for (int j = 0; j < 8; j++)
                    acc[i][j] = fmaf(a[i], b[j], acc[i][j]);
        }
        __syncthreads();
    }

#pragma unroll
    for (int i = 0; i < 8; i++) {
        size_t row = (size_t)(bm + tr + i);
#pragma unroll
        for (int j = 0; j < 8; j++) {
            int col = bn + tc + j;
            float v = acc[i][j] + bias[col];
            if (RELU) v = fmaxf(v, 0.f);
            C[row * N + col] = v;
        }
    }
}

// ---------------- flash attention (fp32, online softmax) -------------------
// grid: (SEQ/64, N_HEADS, BATCH), block 256, dynamic smem 4*64*65*4 bytes
__launch_bounds__(256)
__global__ void attn_kernel(const float* __restrict__ Q,
                            const float* __restrict__ K,
                            const float* __restrict__ V,
                            const int* __restrict__ mask,
                            float* __restrict__ ctx)
{
    constexpr int BQ = 64, BKT = 64, PAD = 65;
    extern __shared__ float sm[];
    float* Qs = sm;                    // BQ  x PAD
    float* Ks = Qs + BQ * PAD;         // BKT x PAD
    float* Vs = Ks + BKT * PAD;        // BKT x PAD
    float* Ps = Vs + BKT * PAD;        // BQ  x PAD

    const int tid = threadIdx.x;
    const int tx = tid & 15, ty = tid >> 4;
    const int r0 = ty * 4, c0 = tx * 4;
    const int qt = blockIdx.x, h = blockIdx.y, b = blockIdx.z;
    const int q0 = qt * BQ;
    const size_t base = (size_t)b * SEQ * D_MODEL + (size_t)h * DK;

    // load Q tile
    for (int i = tid; i < BQ * (DK / 4); i += 256) {
        int r = i >> 4, cv = (i & 15) * 4;
        float4 v4 = *(const float4*)(Q + base + (size_t)(q0 + r) * D_MODEL + cv);
        Qs[r * PAD + cv + 0] = v4.x;
        Qs[r * PAD + cv + 1] = v4.y;
        Qs[r * PAD + cv + 2] = v4.z;
        Qs[r * PAD + cv + 3] = v4.w;
    }

    float m_r[4], l_r[4], acc[4][4];
#pragma unroll
    for (int i = 0; i < 4; i++) {
        m_r[i] = -1e30f; l_r[i] = 0.f;
#pragma unroll
        for (int j = 0; j < 4; j++) acc[i][j] = 0.f;
    }

    for (int kt = 0; kt < SEQ / BKT; kt++) {
        const int k0 = kt * BKT;
        __syncthreads();   // prev iter's Ps/Vs reads done; Qs visible on iter 0
        for (int i = tid; i < BKT * (DK / 4); i += 256) {
            int r = i >> 4, cv = (i & 15) * 4;
            float4 k4 = *(const float4*)(K + base + (size_t)(k0 + r) * D_MODEL + cv);
            Ks[r * PAD + cv + 0] = k4.x;
            Ks[r * PAD + cv + 1] = k4.y;
            Ks[r * PAD + cv + 2] = k4.z;
            Ks[r * PAD + cv + 3] = k4.w;
            float4 v4 = *(const float4*)(V + base + (size_t)(k0 + r) * D_MODEL + cv);
            Vs[r * PAD + cv + 0] = v4.x;
            Vs[r * PAD + cv + 1] = v4.y;
            Vs[r * PAD + cv + 2] = v4.z;
            Vs[r * PAD + cv + 3] = v4.w;
        }
        __syncthreads();

        // scores s = Q @ K^T for this 64x64 tile (4x4 per thread)
        float s[4][4];
#pragma unroll
        for (int i = 0; i < 4; i++)
#pragma unroll
            for (int j = 0; j < 4; j++) s[i][j] = 0.f;
#pragma unroll 16
        for (int d = 0; d < DK; d++) {
            float qa[4], kb[4];
#pragma unroll
            for (int i = 0; i < 4; i++) qa[i] = Qs[(r0 + i) * PAD + d];
#pragma unroll
            for (int j = 0; j < 4; j++) kb[j] = Ks[(c0 + j) * PAD + d];
#pragma unroll
            for (int i = 0; i < 4; i++)
#pragma unroll
                for (int j = 0; j < 4; j++)
                    s[i][j] = fmaf(qa[i], kb[j], s[i][j]);
        }

        // scale + mask
        int mv[4];
#pragma unroll
        for (int j = 0; j < 4; j++) mv[j] = mask[b * SEQ + k0 + c0 + j];
#pragma unroll
        for (int i = 0; i < 4; i++)
#pragma unroll
            for (int j = 0; j < 4; j++) {
                float sv = s[i][j] * 0.125f;   // 1/sqrt(64)
                if (mv[j] == 0) sv = -1e9f;
                s[i][j] = sv;
            }

        // row max across the 16 tx lanes (lanes 0-15 / 16-31 within warp)
        float mt[4];
#pragma unroll
        for (int i = 0; i < 4; i++)
            mt[i] = fmaxf(fmaxf(s[i][0], s[i][1]), fmaxf(s[i][2], s[i][3]));
#pragma unroll
        for (int off = 1; off < 16; off <<= 1)
#pragma unroll
            for (int i = 0; i < 4; i++)
                mt[i] = fmaxf(mt[i], __shfl_xor_sync(0xffffffffu, mt[i], off));

        float p[4][4], lsum[4];
#pragma unroll
        for (int i = 0; i < 4; i++) {
            float mn = fmaxf(m_r[i], mt[i]);
            float al = __expf(m_r[i] - mn);
            m_r[i] = mn;
            lsum[i] = 0.f;
#pragma unroll
            for (int j = 0; j < 4; j++) {
                p[i][j] = __expf(s[i][j] - mn);
                lsum[i] += p[i][j];
            }
#pragma unroll
            for (int j = 0; j < 4; j++) acc[i][j] *= al;
            l_r[i] *= al;
        }
#pragma unroll
        for (int off = 1; off < 16; off <<= 1)
#pragma unroll
            for (int i = 0; i < 4; i++)
                lsum[i] += __shfl_xor_sync(0xffffffffu, lsum[i], off);
#pragma unroll
        for (int i = 0; i < 4; i++) l_r[i] += lsum[i];

        // share p
#pragma unroll
        for (int i = 0; i < 4; i++)
#pragma unroll
            for (int j = 0; j < 4; j++)
                Ps[(r0 + i) * PAD + (c0 + j)] = p[i][j];
        __syncthreads();

        // acc += P @ V (output cols = c0..c0+3 of the 64-wide head dim)
#pragma unroll 8
        for (int c = 0; c < BKT; c++) {
            float pv[4], vv[4];
#pragma unroll
            for (int i = 0; i < 4; i++) pv[i] = Ps[(r0 + i) * PAD + c];
#pragma unroll
            for (int j = 0; j < 4; j++) vv[j] = Vs[c * PAD + c0 + j];
#pragma unroll
            for (int i = 0; i < 4; i++)
#pragma unroll
                for (int j = 0; j < 4; j++)
                    acc[i][j] = fmaf(pv[i], vv[j], acc[i][j]);
        }
    }

    // write ctx in [B, S, H*DK] layout
#pragma unroll
    for (int i = 0; i < 4; i++) {
        float inv = 1.f / l_r[i];
        size_t orow = ((size_t)b * SEQ + q0 + r0 + i) * D_MODEL + (size_t)h * DK + c0;
#pragma unroll
        for (int j = 0; j < 4; j++)
            ctx[orow + j] = acc[i][j] * inv;
    }
}

// ---------------- residual add + LayerNorm ---------------------------------
__launch_bounds__(128)
__global__ void add_ln_kernel(const float* __restrict__ a,
                              const float* __restrict__ r,
                              const float* __restrict__ g,
                              const float* __restrict__ beta,
                              float* __restrict__ out)
{
    const int row = blockIdx.x;
    const int tid = threadIdx.x;
    const size_t off = (size_t)row * D_MODEL;
    float v[4];
    float s = 0.f, ss = 0.f;
#pragma unroll
    for (int i = 0; i < 4; i++) {
        int c = tid + i * 128;
        float x = a[off + c] + r[off + c];
        v[i] = x; s += x; ss += x * x;
    }
#pragma unroll
    for (int o = 16; o > 0; o >>= 1) {
        s  += __shfl_xor_sync(0xffffffffu, s, o);
        ss += __shfl_xor_sync(0xffffffffu, ss, o);
    }
    __shared__ float rs[4], rss[4];
    int w = tid >> 5, lane = tid & 31;
    if (lane == 0) { rs[w] = s; rss[w] = ss; }
    __syncthreads();
    s  = rs[0]  + rs[1]  + rs[2]  + rs[3];
    ss = rss[0] + rss[1] + rss[2] + rss[3];
    float mu   = s * (1.f / D_MODEL);
    float var  = ss * (1.f / D_MODEL) - mu * mu;
    float rstd = rsqrtf(var + 1e-5f);
#pragma unroll
    for (int i = 0; i < 4; i++) {
        int c = tid + i * 128;
        out[off + c] = (v[i] - mu) * rstd * g[c] + beta[c];
    }
}

// ---------------- launch ---------------------------------------------------
extern "C" void kernel_launch(void* const* d_in, const int* in_sizes, int n_in,
                              void* d_out, int out_size)
{
    (void)in_sizes; (void)n_in; (void)out_size;
    const float* x    = (const float*)d_in[0];
    const int*   mask = (const int*)  d_in[1];
    const float* Wq = (const float*)d_in[2];
    const float* bq = (const float*)d_in[3];
    const float* Wk = (const float*)d_in[4];
    const float* bk = (const float*)d_in[5];
    const float* Wv = (const float*)d_in[6];
    const float* bv = (const float*)d_in[7];
    const float* Wo = (const float*)d_in[8];
    const float* bo = (const float*)d_in[9];
    const float* W1 = (const float*)d_in[10];
    const float* b1 = (const float*)d_in[11];
    const float* W2 = (const float*)d_in[12];
    const float* b2 = (const float*)d_in[13];
    const float* g1 = (const float*)d_in[14];
    const float* be1= (const float*)d_in[15];
    const float* g2 = (const float*)d_in[16];
    const float* be2= (const float*)d_in[17];
    float* out = (float*)d_out;

    float *q, *k, *v, *ctx, *x1, *tmp, *ff;
    cudaGetSymbolAddress((void**)&q,   g_q);
    cudaGetSymbolAddress((void**)&k,   g_k);
    cudaGetSymbolAddress((void**)&v,   g_v);
    cudaGetSymbolAddress((void**)&ctx, g_ctx);
    cudaGetSymbolAddress((void**)&x1,  g_x1);
    cudaGetSymbolAddress((void**)&tmp, g_tmp);
    cudaGetSymbolAddress((void**)&ff,  g_ff);

    const int M = NTOK;

    // QKV projections
    {
        dim3 grid(D_MODEL / 128, M / 128);
        sgemm_bias_kernel<false><<<grid, 256>>>(x, Wq, bq, q, M, D_MODEL, D_MODEL);
        sgemm_bias_kernel<false><<<grid, 256>>>(x, Wk, bk, k, M, D_MODEL, D_MODEL);
        sgemm_bias_kernel<false><<<grid, 256>>>(x, Wv, bv, v, M, D_MODEL, D_MODEL);
    }

    // flash attention
    {
        const int smem = 4 * 64 * 65 * (int)sizeof(float);   // 66560 B
        cudaFuncSetAttribute(attn_kernel,
                             cudaFuncAttributeMaxDynamicSharedMemorySize, smem);
        dim3 grid(SEQ / 64, N_HEADS, BATCH);
        attn_kernel<<<grid, 256, smem>>>(q, k, v, mask, ctx);
    }

    // Wo projection -> tmp; x1 = LN(x + tmp)
    {
        dim3 grid(D_MODEL / 128, M / 128);
        sgemm_bias_kernel<false><<<grid, 256>>>(ctx, Wo, bo, tmp, M, D_MODEL, D_MODEL);
        add_ln_kernel<<<M, 128>>>(x, tmp, g1, be1, x1);
    }

    // FF
    {
        dim3 grid1(D_FF / 128, M / 128);
        sgemm_bias_kernel<true><<<grid1, 256>>>(x1, W1, b1, ff, M, D_FF, D_MODEL);
        dim3 grid2(D_MODEL / 128, M / 128);
        sgemm_bias_kernel<false><<<grid2, 256>>>(ff, W2, b2, tmp, M, D_MODEL, D_FF);
        add_ln_kernel<<<M, 128>>>(x1, tmp, g2, be2, out);
    }
}

// round 3
// speedup vs baseline: 1.5494x; 1.5494x over previous
#include <cuda_runtime.h>
#include <cuda_bf16.h>
#include <cstdint>
#include <math.h>

#define D_MODEL 512
#define N_HEADS 8
#define DK      64
#define D_FF    2048
#define BATCH   2
#define SEQ     2048
#define NTOK    (BATCH * SEQ)   // 4096

// ---------------- scratch (device globals; no allocation allowed) ----------
static __device__ float g_q  [(size_t)NTOK * D_MODEL];
static __device__ float g_k  [(size_t)NTOK * D_MODEL];
static __device__ float g_v  [(size_t)NTOK * D_MODEL];
static __device__ float g_x1 [(size_t)NTOK * D_MODEL];
static __device__ float g_tmp[(size_t)NTOK * D_MODEL];

static __device__ __nv_bfloat16 g_xh  [(size_t)NTOK * D_MODEL];
static __device__ __nv_bfloat16 g_xl  [(size_t)NTOK * D_MODEL];
static __device__ __nv_bfloat16 g_ctxh[(size_t)NTOK * D_MODEL];
static __device__ __nv_bfloat16 g_ctxl[(size_t)NTOK * D_MODEL];
static __device__ __nv_bfloat16 g_x1h [(size_t)NTOK * D_MODEL];
static __device__ __nv_bfloat16 g_x1l [(size_t)NTOK * D_MODEL];
static __device__ __nv_bfloat16 g_ffh [(size_t)NTOK * D_FF];
static __device__ __nv_bfloat16 g_ffl [(size_t)NTOK * D_FF];

// transposed + hi/lo-split bf16 weights: Wt[n][k]
#define OFF_WQ  0
#define OFF_WK  (512*512)
#define OFF_WV  (2*512*512)
#define OFF_WO  (3*512*512)
#define OFF_W1  (4*512*512)
#define OFF_W2  (4*512*512 + 2048*512)
#define WT_TOTAL (4*512*512 + 2*2048*512)
static __device__ __nv_bfloat16 g_wt_h[WT_TOTAL];
static __device__ __nv_bfloat16 g_wt_l[WT_TOTAL];

// ======================= PTX helpers (base sm_80+ features) ================
__device__ __forceinline__ uint32_t smem_u32(const void* p) {
    uint32_t a;
    asm("{ .reg .u64 t; cvta.to.shared.u64 t, %1; cvt.u32.u64 %0, t; }"
        : "=r"(a) : "l"(p));
    return a;
}
__device__ __forceinline__ void cp_async16(uint32_t dst, const void* src) {
    asm volatile("cp.async.cg.shared.global [%0], [%1], 16;" :: "r"(dst), "l"(src));
}
#define CP_COMMIT() asm volatile("cp.async.commit_group;" ::: "memory")
#define CP_WAIT1()  asm volatile("cp.async.wait_group 1;" ::: "memory")

__device__ __forceinline__ void ldm_x4(uint32_t* r, uint32_t addr) {
    asm volatile("ldmatrix.sync.aligned.m8n8.x4.shared.b16 {%0,%1,%2,%3}, [%4];"
        : "=r"(r[0]), "=r"(r[1]), "=r"(r[2]), "=r"(r[3]) : "r"(addr));
}
__device__ __forceinline__ void mma_bf16(float* c, const uint32_t* a, const uint32_t* b) {
    asm volatile("mma.sync.aligned.m16n8k16.row.col.f32.bf16.bf16.f32 "
        "{%0,%1,%2,%3}, {%4,%5,%6,%7}, {%8,%9}, {%0,%1,%2,%3};"
        : "+f"(c[0]), "+f"(c[1]), "+f"(c[2]), "+f"(c[3])
        : "r"(a[0]), "r"(a[1]), "r"(a[2]), "r"(a[3]), "r"(b[0]), "r"(b[1]));
}

// ============ weight transpose + hi/lo bf16 split:  Wt[n][k] = W[k][n] ======
__global__ void transpose_split_kernel(const float* __restrict__ W,
                                       __nv_bfloat16* __restrict__ Th,
                                       __nv_bfloat16* __restrict__ Tl,
                                       int K, int N)
{
    __shared__ float tile[32][33];
    const int k0 = blockIdx.y * 32, n0 = blockIdx.x * 32;
    const int tx = threadIdx.x & 31, ty = threadIdx.x >> 5;
    for (int i = ty; i < 32; i += 8)
        tile[i][tx] = W[(size_t)(k0 + i) * N + n0 + tx];
    __syncthreads();
    for (int i = ty; i < 32; i += 8) {
        float v = tile[tx][i];
        __nv_bfloat16 h = __float2bfloat16(v);
        float lo = v - __bfloat162float(h);
        size_t o = (size_t)(n0 + i) * K + k0 + tx;
        Th[o] = h;
        Tl[o] = __float2bfloat16(lo);
    }
}

// ============ elementwise fp32 -> bf16 hi/lo split ==========================
__global__ void split_kernel(const float* __restrict__ X,
                             __nv_bfloat16* __restrict__ Xh,
                             __nv_bfloat16* __restrict__ Xl)
{
    const int i = blockIdx.x * blockDim.x + threadIdx.x;
    float v = X[i];
    __nv_bfloat16 h = __float2bfloat16(v);
    Xh[i] = h;
    Xl[i] = __float2bfloat16(v - __bfloat162float(h));
}

// ================ bf16 tensor-core GEMM: C = A @ B^T + bias ================
// A: hi/lo bf16 [M,K] row-major. B: hi/lo bf16 [N,K] (K-major).
// acc = Ah*Bh + Ah*Bl + Al*Bh  (fp32-accurate).
// Tile 128x128, BK=32, 8 warps (warp tile 64x32), 2-stage cp.async pipeline.
// SMEM stage: 4 tiles (Ah,Al,Bh,Bl) of 128 rows x 80B (32 bf16 + pad) = 40960B.
#define GEMM_SMEM (2 * 40960)
#define ROWB 80          // bytes per smem row (32 bf16 = 64B + 16B pad)
#define TILEB (128 * ROWB)

template <bool RELU, bool SPLIT>
__launch_bounds__(256, 1)
__global__ void sgemm_mma_kernel(const __nv_bfloat16* __restrict__ Ah,
                                 const __nv_bfloat16* __restrict__ Al,
                                 const __nv_bfloat16* __restrict__ Bh,
                                 const __nv_bfloat16* __restrict__ Bl,
                                 const float* __restrict__ bias,
                                 float* __restrict__ C,
                                 __nv_bfloat16* __restrict__ Ch,
                                 __nv_bfloat16* __restrict__ Cl,
                                 int M, int N, int K)
{
    extern __shared__ char smem[];
    const uint32_t sb = smem_u32(smem);
    const int tid = threadIdx.x;
    const int lane = tid & 31, wid = tid >> 5;
    const int wm = wid & 1, wn = wid >> 1;          // warp grid 2 x 4
    const int bm = blockIdx.y * 128;
    const int bn = blockIdx.x * 128;

    // per-thread ldmatrix offsets (within a stage)
    const uint32_t offA = (uint32_t)(wm * 64 + (lane & 15)) * ROWB + (lane >> 4) * 16;
    const uint32_t offB = (uint32_t)(wn * 32 + ((lane & 16) ? 8 : 0) + (lane & 7)) * ROWB
                        + ((lane & 8) ? 16 : 0);

    // cp.async mapping: 2048 16B-chunks per stage, 8 per thread
    const __nv_bfloat16* srcBase[4] = {
        Ah + (size_t)bm * K, Al + (size_t)bm * K,
        Bh + (size_t)bn * K, Bl + (size_t)bn * K };

    const int nchunks = K >> 5;

    auto load_stage = [&](int s, int c) {
        const int k0 = c << 5;
        const uint32_t stg = sb + s * GEMM_SMEM / 2;
#pragma unroll
        for (int i = 0; i < 8; i++) {
            int idx = i * 256 + tid;
            int tile = idx >> 9;
            int rem = idx & 511;
            int r = rem >> 2;
            int ch = rem & 3;
            uint32_t dst = stg + tile * TILEB + (uint32_t)r * ROWB + ch * 16;
            cp_async16(dst, srcBase[tile] + (size_t)r * K + k0 + ch * 8);
        }
    };

    float acc[4][4][4];
#pragma unroll
    for (int i = 0; i < 4; i++)
#pragma unroll
        for (int j = 0; j < 4; j++)
#pragma unroll
            for (int t = 0; t < 4; t++) acc[i][j][t] = 0.f;

    load_stage(0, 0); CP_COMMIT();
    if (nchunks > 1) load_stage(1, 1);
    CP_COMMIT();

    for (int c = 0; c < nchunks; c++) {
        const int s = c & 1;
        CP_WAIT1();
        __syncthreads();

        const uint32_t base = sb + s * (GEMM_SMEM / 2);
        const uint32_t aH = base + offA;
        const uint32_t aL = aH + TILEB;
        const uint32_t bH = base + 2 * TILEB + offB;
        const uint32_t bL = bH + TILEB;

#pragma unroll
        for (int kst = 0; kst < 2; kst++) {
            const uint32_t kb = kst * 32;
            uint32_t fah[4][4], fal[4][4], fbh[2][4], fbl[2][4];
#pragma unroll
            for (int i = 0; i < 4; i++) {
                ldm_x4(fah[i], aH + i * (16 * ROWB) + kb);
                ldm_x4(fal[i], aL + i * (16 * ROWB) + kb);
            }
#pragma unroll
            for (int jj = 0; jj < 2; jj++) {
                ldm_x4(fbh[jj], bH + jj * (16 * ROWB) + kb);
                ldm_x4(fbl[jj], bL + jj * (16 * ROWB) + kb);
            }
#pragma unroll
            for (int i = 0; i < 4; i++)
#pragma unroll
                for (int j = 0; j < 4; j++) {
                    const uint32_t* bhp = &fbh[j >> 1][(j & 1) * 2];
                    const uint32_t* blp = &fbl[j >> 1][(j & 1) * 2];
                    mma_bf16(acc[i][j], fah[i], bhp);
                    mma_bf16(acc[i][j], fah[i], blp);
                    mma_bf16(acc[i][j], fal[i], bhp);
                }
        }
        __syncthreads();
        if (c + 2 < nchunks) load_stage(s, c + 2);
        CP_COMMIT();
    }

    // -------- epilogue --------
    const int tr = lane >> 2;
    const int tc2 = (lane & 3) * 2;
#pragma unroll
    for (int i = 0; i < 4; i++) {
#pragma unroll
        for (int j = 0; j < 4; j++) {
            const int r = bm + wm * 64 + i * 16 + tr;
            const int ccol = bn + wn * 32 + j * 8 + tc2;
            const float b0 = bias[ccol], b1 = bias[ccol + 1];
#pragma unroll
            for (int half = 0; half < 2; half++) {
                float v0 = acc[i][j][half * 2 + 0] + b0;
                float v1 = acc[i][j][half * 2 + 1] + b1;
                if (RELU) { v0 = fmaxf(v0, 0.f); v1 = fmaxf(v1, 0.f); }
                const size_t o = (size_t)(r + half * 8) * N + ccol;
                if (SPLIT) {
                    __nv_bfloat16 h0 = __float2bfloat16(v0);
                    __nv_bfloat16 h1 = __float2bfloat16(v1);
                    __nv_bfloat162 hh; hh.x = h0; hh.y = h1;
                    __nv_bfloat162 ll;
                    ll.x = __float2bfloat16(v0 - __bfloat162float(h0));
                    ll.y = __float2bfloat16(v1 - __bfloat162float(h1));
                    *(__nv_bfloat162*)(Ch + o) = hh;
                    *(__nv_bfloat162*)(Cl + o) = ll;
                } else {
                    *(float2*)(C + o) = make_float2(v0, v1);
                }
            }
        }
    }
}

// ---------------- flash attention (fp32, online softmax) -------------------
// writes ctx as bf16 hi/lo split (only consumer is the Wo GEMM)
__launch_bounds__(256)
__global__ void attn_kernel(const float* __restrict__ Q,
                            const float* __restrict__ K,
                            const float* __restrict__ V,
                            const int* __restrict__ mask,
                            __nv_bfloat16* __restrict__ ctxh,
                            __nv_bfloat16* __restrict__ ctxl)
{
    constexpr int BQ = 64, BKT = 64, PAD = 65;
    extern __shared__ float sm[];
    float* Qs = sm;
    float* Ks = Qs + BQ * PAD;
    float* Vs = Ks + BKT * PAD;
    float* Ps = Vs + BKT * PAD;

    const int tid = threadIdx.x;
    const int tx = tid & 15, ty = tid >> 4;
    const int r0 = ty * 4, c0 = tx * 4;
    const int qt = blockIdx.x, h = blockIdx.y, b = blockIdx.z;
    const int q0 = qt * BQ;
    const size_t base = (size_t)b * SEQ * D_MODEL + (size_t)h * DK;

    for (int i = tid; i < BQ * (DK / 4); i += 256) {
        int r = i >> 4, cv = (i & 15) * 4;
        float4 v4 = *(const float4*)(Q + base + (size_t)(q0 + r) * D_MODEL + cv);
        Qs[r * PAD + cv + 0] = v4.x; Qs[r * PAD + cv + 1] = v4.y;
        Qs[r * PAD + cv + 2] = v4.z; Qs[r * PAD + cv + 3] = v4.w;
    }

    float m_r[4], l_r[4], acc[4][4];
#pragma unroll
    for (int i = 0; i < 4; i++) {
        m_r[i] = -1e30f; l_r[i] = 0.f;
#pragma unroll
        for (int j = 0; j < 4; j++) acc[i][j] = 0.f;
    }

    for (int kt = 0; kt < SEQ / BKT; kt++) {
        const int k0 = kt * BKT;
        __syncthreads();
        for (int i = tid; i < BKT * (DK / 4); i += 256) {
            int r = i >> 4, cv = (i & 15) * 4;
            float4 k4 = *(const float4*)(K + base + (size_t)(k0 + r) * D_MODEL + cv);
            Ks[r * PAD + cv + 0] = k4.x; Ks[r * PAD + cv + 1] = k4.y;
            Ks[r * PAD + cv + 2] = k4.z; Ks[r * PAD + cv + 3] = k4.w;
            float4 v4 = *(const float4*)(V + base + (size_t)(k0 + r) * D_MODEL + cv);
            Vs[r * PAD + cv + 0] = v4.x; Vs[r * PAD + cv + 1] = v4.y;
            Vs[r * PAD + cv + 2] = v4.z; Vs[r * PAD + cv + 3] = v4.w;
        }
        __syncthreads();

        float s[4][4];
#pragma unroll
        for (int i = 0; i < 4; i++)
#pragma unroll
            for (int j = 0; j < 4; j++) s[i][j] = 0.f;
#pragma unroll 16
        for (int d = 0; d < DK; d++) {
            float qa[4], kb[4];
#pragma unroll
            for (int i = 0; i < 4; i++) qa[i] = Qs[(r0 + i) * PAD + d];
#pragma unroll
            for (int j = 0; j < 4; j++) kb[j] = Ks[(c0 + j) * PAD + d];
#pragma unroll
            for (int i = 0; i < 4; i++)
#pragma unroll
                for (int j = 0; j < 4; j++)
                    s[i][j] = fmaf(qa[i], kb[j], s[i][j]);
        }

        int mv[4];
#pragma unroll
        for (int j = 0; j < 4; j++) mv[j] = mask[b * SEQ + k0 + c0 + j];
#pragma unroll
        for (int i = 0; i < 4; i++)
#pragma unroll
            for (int j = 0; j < 4; j++) {
                float sv = s[i][j] * 0.125f;
                if (mv[j] == 0) sv = -1e9f;
                s[i][j] = sv;
            }

        float mt[4];
#pragma unroll
        for (int i = 0; i < 4; i++)
            mt[i] = fmaxf(fmaxf(s[i][0], s[i][1]), fmaxf(s[i][2], s[i][3]));
#pragma unroll
        for (int off = 1; off < 16; off <<= 1)
#pragma unroll
            for (int i = 0; i < 4; i++)
                mt[i] = fmaxf(mt[i], __shfl_xor_sync(0xffffffffu, mt[i], off));

        float p[4][4], lsum[4];
#pragma unroll
        for (int i = 0; i < 4; i++) {
            float mn = fmaxf(m_r[i], mt[i]);
            float al = __expf(m_r[i] - mn);
            m_r[i] = mn;
            lsum[i] = 0.f;
#pragma unroll
            for (int j = 0; j < 4; j++) {
                p[i][j] = __expf(s[i][j] - mn);
                lsum[i] += p[i][j];
            }
#pragma unroll
            for (int j = 0; j < 4; j++) acc[i][j] *= al;
            l_r[i] *= al;
        }
#pragma unroll
        for (int off = 1; off < 16; off <<= 1)
#pragma unroll
            for (int i = 0; i < 4; i++)
                lsum[i] += __shfl_xor_sync(0xffffffffu, lsum[i], off);
#pragma unroll
        for (int i = 0; i < 4; i++) l_r[i] += lsum[i];

#pragma unroll
        for (int i = 0; i < 4; i++)
#pragma unroll
            for (int j = 0; j < 4; j++)
                Ps[(r0 + i) * PAD + (c0 + j)] = p[i][j];
        __syncthreads();

#pragma unroll 8
        for (int c = 0; c < BKT; c++) {
            float pv[4], vv[4];
#pragma unroll
            for (int i = 0; i < 4; i++) pv[i] = Ps[(r0 + i) * PAD + c];
#pragma unroll
            for (int j = 0; j < 4; j++) vv[j] = Vs[c * PAD + c0 + j];
#pragma unroll
            for (int i = 0; i < 4; i++)
#pragma unroll
                for (int j = 0; j < 4; j++)
                    acc[i][j] = fmaf(pv[i], vv[j], acc[i][j]);
        }
    }

#pragma unroll
    for (int i = 0; i < 4; i++) {
        float inv = 1.f / l_r[i];
        size_t orow = ((size_t)b * SEQ + q0 + r0 + i) * D_MODEL + (size_t)h * DK + c0;
        float o[4];
#pragma unroll
        for (int j = 0; j < 4; j++) o[j] = acc[i][j] * inv;
#pragma unroll
        for (int half = 0; half < 2; half++) {
            float v0 = o[half * 2], v1 = o[half * 2 + 1];
            __nv_bfloat16 h0 = __float2bfloat16(v0);
            __nv_bfloat16 h1 = __float2bfloat16(v1);
            __nv_bfloat162 hh; hh.x = h0; hh.y = h1;
            __nv_bfloat162 ll;
            ll.x = __float2bfloat16(v0 - __bfloat162float(h0));
            ll.y = __float2bfloat16(v1 - __bfloat162float(h1));
            *(__nv_bfloat162*)(ctxh + orow + half * 2) = hh;
            *(__nv_bfloat162*)(ctxl + orow + half * 2) = ll;
        }
    }
}

// ---------------- residual add + LayerNorm (optional split output) ---------
template <bool SPLIT>
__launch_bounds__(128)
__global__ void add_ln_kernel(const float* __restrict__ a,
                              const float* __restrict__ r,
                              const float* __restrict__ g,
                              const float* __restrict__ beta,
                              float* __restrict__ out,
                              __nv_bfloat16* __restrict__ oh,
                              __nv_bfloat16* __restrict__ ol)
{
    const int row = blockIdx.x;
    const int tid = threadIdx.x;
    const size_t off = (size_t)row * D_MODEL;
    float v[4];
    float s = 0.f, ss = 0.f;
#pragma unroll
    for (int i = 0; i < 4; i++) {
        int c = tid + i * 128;
        float x = a[off + c] + r[off + c];
        v[i] = x; s += x; ss += x * x;
    }
#pragma unroll
    for (int o = 16; o > 0; o >>= 1) {
        s  += __shfl_xor_sync(0xffffffffu, s, o);
        ss += __shfl_xor_sync(0xffffffffu, ss, o);
    }
    __shared__ float rs[4], rss[4];
    int w = tid >> 5, lane = tid & 31;
    if (lane == 0) { rs[w] = s; rss[w] = ss; }
    __syncthreads();
    s  = rs[0]  + rs[1]  + rs[2]  + rs[3];
    ss = rss[0] + rss[1] + rss[2] + rss[3];
    float mu   = s * (1.f / D_MODEL);
    float var  = ss * (1.f / D_MODEL) - mu * mu;
    float rstd = rsqrtf(var + 1e-5f);
#pragma unroll
    for (int i = 0; i < 4; i++) {
        int c = tid + i * 128;
        float y = (v[i] - mu) * rstd * g[c] + beta[c];
        out[off + c] = y;
        if (SPLIT) {
            __nv_bfloat16 h = __float2bfloat16(y);
            oh[off + c] = h;
            ol[off + c] = __float2bfloat16(y - __bfloat162float(h));
        }
    }
}

// ---------------- launch ---------------------------------------------------
extern "C" void kernel_launch(void* const* d_in, const int* in_sizes, int n_in,
                              void* d_out, int out_size)
{
    (void)in_sizes; (void)n_in; (void)out_size;
    const float* x    = (const float*)d_in[0];
    const int*   mask = (const int*)  d_in[1];
    const float* Wq = (const float*)d_in[2];
    const float* bq = (const float*)d_in[3];
    const float* Wk = (const float*)d_in[4];
    const float* bk = (const float*)d_in[5];
    const float* Wv = (const float*)d_in[6];
    const float* bv = (const float*)d_in[7];
    const float* Wo = (const float*)d_in[8];
    const float* bo = (const float*)d_in[9];
    const float* W1 = (const float*)d_in[10];
    const float* b1 = (const float*)d_in[11];
    const float* W2 = (const float*)d_in[12];
    const float* b2 = (const float*)d_in[13];
    const float* g1 = (const float*)d_in[14];
    const float* be1= (const float*)d_in[15];
    const float* g2 = (const float*)d_in[16];
    const float* be2= (const float*)d_in[17];
    float* out = (float*)d_out;

    float *q, *k, *v, *x1, *tmp;
    __nv_bfloat16 *wh, *wl, *xh, *xl, *ctxh, *ctxl, *x1h, *x1l, *ffh, *ffl;
    cudaGetSymbolAddress((void**)&q,    g_q);
    cudaGetSymbolAddress((void**)&k,    g_k);
    cudaGetSymbolAddress((void**)&v,    g_v);
    cudaGetSymbolAddress((void**)&x1,   g_x1);
    cudaGetSymbolAddress((void**)&tmp,  g_tmp);
    cudaGetSymbolAddress((void**)&wh,   g_wt_h);
    cudaGetSymbolAddress((void**)&wl,   g_wt_l);
    cudaGetSymbolAddress((void**)&xh,   g_xh);
    cudaGetSymbolAddress((void**)&xl,   g_xl);
    cudaGetSymbolAddress((void**)&ctxh, g_ctxh);
    cudaGetSymbolAddress((void**)&ctxl, g_ctxl);
    cudaGetSymbolAddress((void**)&x1h,  g_x1h);
    cudaGetSymbolAddress((void**)&x1l,  g_x1l);
    cudaGetSymbolAddress((void**)&ffh,  g_ffh);
    cudaGetSymbolAddress((void**)&ffl,  g_ffl);

    cudaFuncSetAttribute(sgemm_mma_kernel<false, false>,
                         cudaFuncAttributeMaxDynamicSharedMemorySize, GEMM_SMEM);
    cudaFuncSetAttribute(sgemm_mma_kernel<true, true>,
                         cudaFuncAttributeMaxDynamicSharedMemorySize, GEMM_SMEM);

    const int M = NTOK;

    // ---- weight transpose + split; input split ----
    transpose_split_kernel<<<dim3(16, 16), 256>>>(Wq, wh + OFF_WQ, wl + OFF_WQ, 512, 512);
    transpose_split_kernel<<<dim3(16, 16), 256>>>(Wk, wh + OFF_WK, wl + OFF_WK, 512, 512);
    transpose_split_kernel<<<dim3(16, 16), 256>>>(Wv, wh + OFF_WV, wl + OFF_WV, 512, 512);
    transpose_split_kernel<<<dim3(16, 16), 256>>>(Wo, wh + OFF_WO, wl + OFF_WO, 512, 512);
    transpose_split_kernel<<<dim3(64, 16), 256>>>(W1, wh + OFF_W1, wl + OFF_W1, 512, 2048);
    transpose_split_kernel<<<dim3(16, 64), 256>>>(W2, wh + OFF_W2, wl + OFF_W2, 2048, 512);
    split_kernel<<<NTOK * D_MODEL / 256, 256>>>(x, xh, xl);

    // ---- QKV projections (tensor cores) ----
    {
        dim3 grid(512 / 128, M / 128);
        sgemm_mma_kernel<false, false><<<grid, 256, GEMM_SMEM>>>(
            xh, xl, wh + OFF_WQ, wl + OFF_WQ, bq, q, nullptr, nullptr, M, 512, 512);
        sgemm_mma_kernel<false, false><<<grid, 256, GEMM_SMEM>>>(
            xh, xl, wh + OFF_WK, wl + OFF_WK, bk, k, nullptr, nullptr, M, 512, 512);
        sgemm_mma_kernel<false, false><<<grid, 256, GEMM_SMEM>>>(
            xh, xl, wh + OFF_WV, wl + OFF_WV, bv, v, nullptr, nullptr, M, 512, 512);
    }

    // ---- flash attention (writes ctx split) ----
    {
        const int smem = 4 * 64 * 65 * (int)sizeof(float);
        cudaFuncSetAttribute(attn_kernel,
                             cudaFuncAttributeMaxDynamicSharedMemorySize, smem);
        dim3 grid(SEQ / 64, N_HEADS, BATCH);
        attn_kernel<<<grid, 256, smem>>>(q, k, v, mask, ctxh, ctxl);
    }

    // ---- Wo projection; x1 = LN(x + attn_out) (+ split for FF1) ----
    {
        dim3 grid(512 / 128, M / 128);
        sgemm_mma_kernel<false, false><<<grid, 256, GEMM_SMEM>>>(
            ctxh, ctxl, wh + OFF_WO, wl + OFF_WO, bo, tmp, nullptr, nullptr, M, 512, 512);
        add_ln_kernel<true><<<M, 128>>>(x, tmp, g1, be1, x1, x1h, x1l);
    }

    // ---- FF ----
    {
        dim3 grid1(2048 / 128, M / 128);
        sgemm_mma_kernel<true, true><<<grid1, 256, GEMM_SMEM>>>(
            x1h, x1l, wh + OFF_W1, wl + OFF_W1, b1, nullptr, ffh, ffl, M, 2048, 512);
        dim3 grid2(512 / 128, M / 128);
        sgemm_mma_kernel<false, false><<<grid2, 256, GEMM_SMEM>>>(
            ffh, ffl, wh + OFF_W2, wl + OFF_W2, b2, tmp, nullptr, nullptr, M, 512, 2048);
        add_ln_kernel<false><<<M, 128>>>(x1, tmp, g2, be2, out, nullptr, nullptr);
    }
}

// round 4
// speedup vs baseline: 2.8507x; 1.8399x over previous
#include <cuda_runtime.h>
#include <cuda_bf16.h>
#include <cstdint>
#include <math.h>

#define D_MODEL 512
#define N_HEADS 8
#define DK      64
#define D_FF    2048
#define BATCH   2
#define SEQ     2048
#define NTOK    (BATCH * SEQ)   // 4096

#define SCALE_Q 0.18033688011112042f   // 0.125 * log2(e)

// ---------------- scratch (device globals; no allocation allowed) ----------
static __device__ float g_x1 [(size_t)NTOK * D_MODEL];
static __device__ float g_tmp[(size_t)NTOK * D_MODEL];

static __device__ __nv_bfloat16 g_xh  [(size_t)NTOK * D_MODEL];
static __device__ __nv_bfloat16 g_xl  [(size_t)NTOK * D_MODEL];
static __device__ __nv_bfloat16 g_qh  [(size_t)NTOK * D_MODEL];
static __device__ __nv_bfloat16 g_ql  [(size_t)NTOK * D_MODEL];
static __device__ __nv_bfloat16 g_kh  [(size_t)NTOK * D_MODEL];
static __device__ __nv_bfloat16 g_kl  [(size_t)NTOK * D_MODEL];
static __device__ __nv_bfloat16 g_vh  [(size_t)NTOK * D_MODEL];
static __device__ __nv_bfloat16 g_vl  [(size_t)NTOK * D_MODEL];
static __device__ __nv_bfloat16 g_ctxh[(size_t)NTOK * D_MODEL];
static __device__ __nv_bfloat16 g_ctxl[(size_t)NTOK * D_MODEL];
static __device__ __nv_bfloat16 g_x1h [(size_t)NTOK * D_MODEL];
static __device__ __nv_bfloat16 g_x1l [(size_t)NTOK * D_MODEL];
static __device__ __nv_bfloat16 g_ffh [(size_t)NTOK * D_FF];
static __device__ __nv_bfloat16 g_ffl [(size_t)NTOK * D_FF];

#define OFF_WQ  0
#define OFF_WK  (512*512)
#define OFF_WV  (2*512*512)
#define OFF_WO  (3*512*512)
#define OFF_W1  (4*512*512)
#define OFF_W2  (4*512*512 + 2048*512)
#define WT_TOTAL (4*512*512 + 2*2048*512)
static __device__ __nv_bfloat16 g_wt_h[WT_TOTAL];
static __device__ __nv_bfloat16 g_wt_l[WT_TOTAL];

// ======================= PTX helpers (base sm_80+ features) ================
__device__ __forceinline__ uint32_t smem_u32(const void* p) {
    uint32_t a;
    asm("{ .reg .u64 t; cvta.to.shared.u64 t, %1; cvt.u32.u64 %0, t; }"
        : "=r"(a) : "l"(p));
    return a;
}
__device__ __forceinline__ void cp_async16(uint32_t dst, const void* src) {
    asm volatile("cp.async.cg.shared.global [%0], [%1], 16;" :: "r"(dst), "l"(src));
}
#define CP_COMMIT() asm volatile("cp.async.commit_group;" ::: "memory")
#define CP_WAIT1()  asm volatile("cp.async.wait_group 1;" ::: "memory")

__device__ __forceinline__ void ldm_x4(uint32_t* r, uint32_t addr) {
    asm volatile("ldmatrix.sync.aligned.m8n8.x4.shared.b16 {%0,%1,%2,%3}, [%4];"
        : "=r"(r[0]), "=r"(r[1]), "=r"(r[2]), "=r"(r[3]) : "r"(addr));
}
__device__ __forceinline__ void ldm_x4_t(uint32_t* r, uint32_t addr) {
    asm volatile("ldmatrix.sync.aligned.m8n8.x4.trans.shared.b16 {%0,%1,%2,%3}, [%4];"
        : "=r"(r[0]), "=r"(r[1]), "=r"(r[2]), "=r"(r[3]) : "r"(addr));
}
__device__ __forceinline__ void mma_bf16(float* c, const uint32_t* a, const uint32_t* b) {
    asm volatile("mma.sync.aligned.m16n8k16.row.col.f32.bf16.bf16.f32 "
        "{%0,%1,%2,%3}, {%4,%5,%6,%7}, {%8,%9}, {%0,%1,%2,%3};"
        : "+f"(c[0]), "+f"(c[1]), "+f"(c[2]), "+f"(c[3])
        : "r"(a[0]), "r"(a[1]), "r"(a[2]), "r"(a[3]), "r"(b[0]), "r"(b[1]));
}
// pack (lo, hi) -> bf16x2 (lo in low half)
__device__ __forceinline__ uint32_t pack_bf16x2(float lo, float hi) {
    uint32_t r;
    asm("cvt.rn.bf16x2.f32 %0, %1, %2;" : "=r"(r) : "f"(hi), "f"(lo));
    return r;
}

// fast exp2 for x <= 0 on the FMA pipe (no MUFU). abs err ~2e-6.
__device__ __forceinline__ float exp2p(float x) {
    x = fmaxf(x, -126.f);
    float t = __fadd_rn(x, 12582912.f);          // round to nearest int
    float n = __fadd_rn(t, -12582912.f);
    float f = x - n;                              // f in [-0.5, 0.5]
    float p = 1.3333558146e-3f;
    p = fmaf(p, f, 9.6181291077e-3f);
    p = fmaf(p, f, 5.5504108665e-2f);
    p = fmaf(p, f, 2.4022650696e-1f);
    p = fmaf(p, f, 6.9314718056e-1f);
    p = fmaf(p, f, 1.0f);
    int e = __float_as_int(t) - 0x4B400000;       // = (int)n
    return p * __int_as_float((e + 127) << 23);
}

// ============ weight transpose + hi/lo bf16 split:  Wt[n][k] = W[k][n] ======
__global__ void transpose_split_kernel(const float* __restrict__ W,
                                       __nv_bfloat16* __restrict__ Th,
                                       __nv_bfloat16* __restrict__ Tl,
                                       int K, int N)
{
    __shared__ float tile[32][33];
    const int k0 = blockIdx.y * 32, n0 = blockIdx.x * 32;
    const int tx = threadIdx.x & 31, ty = threadIdx.x >> 5;
    for (int i = ty; i < 32; i += 8)
        tile[i][tx] = W[(size_t)(k0 + i) * N + n0 + tx];
    __syncthreads();
    for (int i = ty; i < 32; i += 8) {
        float v = tile[tx][i];
        __nv_bfloat16 h = __float2bfloat16(v);
        float lo = v - __bfloat162float(h);
        size_t o = (size_t)(n0 + i) * K + k0 + tx;
        Th[o] = h;
        Tl[o] = __float2bfloat16(lo);
    }
}

// ============ elementwise fp32 -> bf16 hi/lo split ==========================
__global__ void split_kernel(const float* __restrict__ X,
                             __nv_bfloat16* __restrict__ Xh,
                             __nv_bfloat16* __restrict__ Xl)
{
    const int i = blockIdx.x * blockDim.x + threadIdx.x;
    float v = X[i];
    __nv_bfloat16 h = __float2bfloat16(v);
    Xh[i] = h;
    Xl[i] = __float2bfloat16(v - __bfloat162float(h));
}

// ================ bf16 tensor-core GEMM: C = A @ B^T + bias ================
// acc = Ah*Bh + Ah*Bl + Al*Bh. Tile 128x128, BK=32, 8 warps, 2-stage cp.async.
#define GEMM_SMEM (2 * 40960)
#define ROWB 80
#define TILEB (128 * ROWB)

template <bool RELU, bool SPLIT>
__launch_bounds__(256, 1)
__global__ void sgemm_mma_kernel(const __nv_bfloat16* __restrict__ Ah,
                                 const __nv_bfloat16* __restrict__ Al,
                                 const __nv_bfloat16* __restrict__ Bh,
                                 const __nv_bfloat16* __restrict__ Bl,
                                 const float* __restrict__ bias,
                                 float* __restrict__ C,
                                 __nv_bfloat16* __restrict__ Ch,
                                 __nv_bfloat16* __restrict__ Cl,
                                 int M, int N, int K, float scale)
{
    extern __shared__ char smem[];
    const uint32_t sb = smem_u32(smem);
    const int tid = threadIdx.x;
    const int lane = tid & 31, wid = tid >> 5;
    const int wm = wid & 1, wn = wid >> 1;
    const int bm = blockIdx.y * 128;
    const int bn = blockIdx.x * 128;

    const uint32_t offA = (uint32_t)(wm * 64 + (lane & 15)) * ROWB + (lane >> 4) * 16;
    const uint32_t offB = (uint32_t)(wn * 32 + ((lane & 16) ? 8 : 0) + (lane & 7)) * ROWB
                        + ((lane & 8) ? 16 : 0);

    const __nv_bfloat16* srcBase[4] = {
        Ah + (size_t)bm * K, Al + (size_t)bm * K,
        Bh + (size_t)bn * K, Bl + (size_t)bn * K };

    const int nchunks = K >> 5;

    auto load_stage = [&](int s, int c) {
        const int k0 = c << 5;
        const uint32_t stg = sb + s * GEMM_SMEM / 2;
#pragma unroll
        for (int i = 0; i < 8; i++) {
            int idx = i * 256 + tid;
            int tile = idx >> 9;
            int rem = idx & 511;
            int r = rem >> 2;
            int ch = rem & 3;
            uint32_t dst = stg + tile * TILEB + (uint32_t)r * ROWB + ch * 16;
            cp_async16(dst, srcBase[tile] + (size_t)r * K + k0 + ch * 8);
        }
    };

    float acc[4][4][4];
#pragma unroll
    for (int i = 0; i < 4; i++)
#pragma unroll
        for (int j = 0; j < 4; j++)
#pragma unroll
            for (int t = 0; t < 4; t++) acc[i][j][t] = 0.f;

    load_stage(0, 0); CP_COMMIT();
    if (nchunks > 1) load_stage(1, 1);
    CP_COMMIT();

    for (int c = 0; c < nchunks; c++) {
        const int s = c & 1;
        CP_WAIT1();
        __syncthreads();

        const uint32_t base = sb + s * (GEMM_SMEM / 2);
        const uint32_t aH = base + offA;
        const uint32_t aL = aH + TILEB;
        const uint32_t bH = base + 2 * TILEB + offB;
        const uint32_t bL = bH + TILEB;

#pragma unroll
        for (int kst = 0; kst < 2; kst++) {
            const uint32_t kb = kst * 32;
            uint32_t fah[4][4], fal[4][4], fbh[2][4], fbl[2][4];
#pragma unroll
            for (int i = 0; i < 4; i++) {
                ldm_x4(fah[i], aH + i * (16 * ROWB) + kb);
                ldm_x4(fal[i], aL + i * (16 * ROWB) + kb);
            }
#pragma unroll
            for (int jj = 0; jj < 2; jj++) {
                ldm_x4(fbh[jj], bH + jj * (16 * ROWB) + kb);
                ldm_x4(fbl[jj], bL + jj * (16 * ROWB) + kb);
            }
#pragma unroll
            for (int i = 0; i < 4; i++)
#pragma unroll
                for (int j = 0; j < 4; j++) {
                    const uint32_t* bhp = &fbh[j >> 1][(j & 1) * 2];
                    const uint32_t* blp = &fbl[j >> 1][(j & 1) * 2];
                    mma_bf16(acc[i][j], fah[i], bhp);
                    mma_bf16(acc[i][j], fah[i], blp);
                    mma_bf16(acc[i][j], fal[i], bhp);
                }
        }
        __syncthreads();
        if (c + 2 < nchunks) load_stage(s, c + 2);
        CP_COMMIT();
    }

    const int tr = lane >> 2;
    const int tc2 = (lane & 3) * 2;
#pragma unroll
    for (int i = 0; i < 4; i++) {
#pragma unroll
        for (int j = 0; j < 4; j++) {
            const int r = bm + wm * 64 + i * 16 + tr;
            const int ccol = bn + wn * 32 + j * 8 + tc2;
            const float b0 = bias[ccol], b1 = bias[ccol + 1];
#pragma unroll
            for (int half = 0; half < 2; half++) {
                float v0 = acc[i][j][half * 2 + 0] + b0;
                float v1 = acc[i][j][half * 2 + 1] + b1;
                if (RELU) { v0 = fmaxf(v0, 0.f); v1 = fmaxf(v1, 0.f); }
                v0 *= scale; v1 *= scale;
                const size_t o = (size_t)(r + half * 8) * N + ccol;
                if (SPLIT) {
                    __nv_bfloat16 h0 = __float2bfloat16(v0);
                    __nv_bfloat16 h1 = __float2bfloat16(v1);
                    __nv_bfloat162 hh; hh.x = h0; hh.y = h1;
                    __nv_bfloat162 ll;
                    ll.x = __float2bfloat16(v0 - __bfloat162float(h0));
                    ll.y = __float2bfloat16(v1 - __bfloat162float(h1));
                    *(__nv_bfloat162*)(Ch + o) = hh;
                    *(__nv_bfloat162*)(Cl + o) = ll;
                } else {
                    *(float2*)(C + o) = make_float2(v0, v1);
                }
            }
        }
    }
}

// ================== tensor-core flash attention =============================
// 128 q-rows per CTA, 8 warps (16 rows each), kv tiles of 64 tokens.
// Q pre-scaled by 0.125*log2e; softmax in base-2 with poly exp2 (FMA pipe).
// smem: madd[2048]f (8KB) | Qh 16KB | Ql 16KB | 2 stages x (kh,kl,vh,vl 8KB each)
#define ATT_SMEM (8192 + 32768 + 2 * 32768)

__launch_bounds__(256, 1)
__global__ void attn_mma_kernel(const __nv_bfloat16* __restrict__ qh,
                                const __nv_bfloat16* __restrict__ ql,
                                const __nv_bfloat16* __restrict__ kh,
                                const __nv_bfloat16* __restrict__ kl,
                                const __nv_bfloat16* __restrict__ vh,
                                const __nv_bfloat16* __restrict__ vl,
                                const int* __restrict__ mask,
                                __nv_bfloat16* __restrict__ ctxh,
                                __nv_bfloat16* __restrict__ ctxl)
{
    extern __shared__ char smc[];
    const uint32_t sb = smem_u32(smc);
    const int tid = threadIdx.x, lane = tid & 31, w = tid >> 5;
    const int qt = blockIdx.x, h = blockIdx.y, b = blockIdx.z;
    const int q0 = qt * 128;
    const size_t qbase  = ((size_t)(b * SEQ + q0)) * D_MODEL + h * DK;
    const size_t kvbase = ((size_t)(b * SEQ)) * D_MODEL + h * DK;

    float* madd = (float*)smc;
    for (int i = tid; i < SEQ; i += 256)
        madd[i] = (mask[b * SEQ + i] == 0) ? -1e9f : 0.f;

    auto load_kv = [&](int s, int ktile) {
        const uint32_t stg = sb + 40960 + s * 32768;
        const size_t tokbase = kvbase + (size_t)ktile * 64 * D_MODEL;
        const __nv_bfloat16* srcs[4] = { kh + tokbase, kl + tokbase,
                                         vh + tokbase, vl + tokbase };
#pragma unroll
        for (int i = 0; i < 8; i++) {
            int idx = i * 256 + tid;
            int t4 = idx >> 9;
            int rem = idx & 511;
            int r = rem >> 3, c = rem & 7;
            uint32_t off = (uint32_t)r * 128 + (uint32_t)((c ^ (r & 7)) << 4);
            cp_async16(stg + t4 * 8192 + off, srcs[t4] + (size_t)r * D_MODEL + c * 8);
        }
    };

    // prologue: Q + stage0 (group A), stage1 (group B)
#pragma unroll
    for (int i = 0; i < 4; i++) {
        int idx = i * 256 + tid;
        int r = idx >> 3, c = idx & 7;
        uint32_t off = (uint32_t)r * 128 + (uint32_t)((c ^ (r & 7)) << 4);
        cp_async16(sb + 8192 + off,  qh + qbase + (size_t)r * D_MODEL + c * 8);
        cp_async16(sb + 24576 + off, ql + qbase + (size_t)r * D_MODEL + c * 8);
    }
    load_kv(0, 0);
    CP_COMMIT();
    load_kv(1, 1);
    CP_COMMIT();

    CP_WAIT1();
    __syncthreads();

    // Q fragments (held in registers for the whole kernel)
    uint32_t qfh[4][4], qfl[4][4];
    {
        const uint32_t qrow = (uint32_t)(w * 16 + (lane & 15));
        const uint32_t qc = (uint32_t)(lane >> 4);
#pragma unroll
        for (int ks = 0; ks < 4; ks++) {
            uint32_t c16 = ks * 2 + qc;
            uint32_t off = qrow * 128 + ((c16 ^ (qrow & 7)) << 4);
            ldm_x4(qfh[ks], sb + 8192 + off);
            ldm_x4(qfl[ks], sb + 24576 + off);
        }
    }

    float m0 = -1e30f, m1 = -1e30f, l0 = 0.f, l1 = 0.f;
    float O[8][4];
#pragma unroll
    for (int g = 0; g < 8; g++)
#pragma unroll
        for (int t = 0; t < 4; t++) O[g][t] = 0.f;

    const uint32_t kr_base = (uint32_t)(((lane & 16) ? 8 : 0) + (lane & 7));
    const uint32_t kc_add  = (uint32_t)((lane & 8) ? 1 : 0);
    const uint32_t vr_base = (uint32_t)(lane & 15);
    const uint32_t vc_add  = (uint32_t)(lane >> 4);

    for (int kt = 0; kt < SEQ / 64; kt++) {
        if (kt > 0) { CP_WAIT1(); __syncthreads(); }
        const uint32_t stg = sb + 40960 + (kt & 1) * 32768;

        // ---- S = Q @ K^T (3 split products) ----
        float S[8][4];
#pragma unroll
        for (int g = 0; g < 8; g++)
#pragma unroll
            for (int t = 0; t < 4; t++) S[g][t] = 0.f;

#pragma unroll
        for (int tg = 0; tg < 4; tg++) {
            const uint32_t row = tg * 16 + kr_base;
#pragma unroll
            for (int ks = 0; ks < 4; ks++) {
                uint32_t c16 = ks * 2 + kc_add;
                uint32_t off = row * 128 + ((c16 ^ (row & 7)) << 4);
                uint32_t fh[4], fl[4];
                ldm_x4(fh, stg + off);
                ldm_x4(fl, stg + 8192 + off);
                mma_bf16(S[2 * tg],     qfh[ks], &fh[0]);
                mma_bf16(S[2 * tg],     qfh[ks], &fl[0]);
                mma_bf16(S[2 * tg],     qfl[ks], &fh[0]);
                mma_bf16(S[2 * tg + 1], qfh[ks], &fh[2]);
                mma_bf16(S[2 * tg + 1], qfh[ks], &fl[2]);
                mma_bf16(S[2 * tg + 1], qfl[ks], &fh[2]);
            }
        }

        // ---- mask + online softmax (base 2) ----
        float mt0 = -1e30f, mt1 = -1e30f;
#pragma unroll
        for (int g = 0; g < 8; g++) {
            float2 ma = *(float2*)&madd[kt * 64 + g * 8 + (lane & 3) * 2];
            S[g][0] += ma.x; S[g][1] += ma.y;
            S[g][2] += ma.x; S[g][3] += ma.y;
            mt0 = fmaxf(mt0, fmaxf(S[g][0], S[g][1]));
            mt1 = fmaxf(mt1, fmaxf(S[g][2], S[g][3]));
        }
        mt0 = fmaxf(mt0, __shfl_xor_sync(0xffffffffu, mt0, 1));
        mt0 = fmaxf(mt0, __shfl_xor_sync(0xffffffffu, mt0, 2));
        mt1 = fmaxf(mt1, __shfl_xor_sync(0xffffffffu, mt1, 1));
        mt1 = fmaxf(mt1, __shfl_xor_sync(0xffffffffu, mt1, 2));

        const float mn0 = fmaxf(m0, mt0), mn1 = fmaxf(m1, mt1);
        const float a0 = exp2p(m0 - mn0), a1 = exp2p(m1 - mn1);
        m0 = mn0; m1 = mn1;

        float s0 = 0.f, s1 = 0.f;
        uint32_t ph[4][4], pl[4][4];
#pragma unroll
        for (int g = 0; g < 8; g++) {
            float p0 = exp2p(S[g][0] - m0);
            float p1 = exp2p(S[g][1] - m0);
            float p2 = exp2p(S[g][2] - m1);
            float p3 = exp2p(S[g][3] - m1);
            s0 += p0 + p1; s1 += p2 + p3;
            uint32_t h01 = pack_bf16x2(p0, p1);
            uint32_t h23 = pack_bf16x2(p2, p3);
            float r0f = __uint_as_float(h01 << 16);
            float r1f = __uint_as_float(h01 & 0xFFFF0000u);
            float r2f = __uint_as_float(h23 << 16);
            float r3f = __uint_as_float(h23 & 0xFFFF0000u);
            uint32_t l01 = pack_bf16x2(p0 - r0f, p1 - r1f);
            uint32_t l23 = pack_bf16x2(p2 - r2f, p3 - r3f);
            ph[g >> 1][(g & 1) * 2 + 0] = h01;
            ph[g >> 1][(g & 1) * 2 + 1] = h23;
            pl[g >> 1][(g & 1) * 2 + 0] = l01;
            pl[g >> 1][(g & 1) * 2 + 1] = l23;
        }
        s0 += __shfl_xor_sync(0xffffffffu, s0, 1);
        s0 += __shfl_xor_sync(0xffffffffu, s0, 2);
        s1 += __shfl_xor_sync(0xffffffffu, s1, 1);
        s1 += __shfl_xor_sync(0xffffffffu, s1, 2);
        l0 = l0 * a0 + s0;
        l1 = l1 * a1 + s1;

#pragma unroll
        for (int g = 0; g < 8; g++) {
            O[g][0] *= a0; O[g][1] *= a0;
            O[g][2] *= a1; O[g][3] *= a1;
        }

        // ---- O += P @ V (3 split products) ----
#pragma unroll
        for (int gp = 0; gp < 4; gp++) {
#pragma unroll
            for (int j2 = 0; j2 < 4; j2++) {
                uint32_t row = j2 * 16 + vr_base;
                uint32_t c16 = gp * 2 + vc_add;
                uint32_t off = row * 128 + ((c16 ^ (row & 7)) << 4);
                uint32_t fh[4], fl[4];
                ldm_x4_t(fh, stg + 16384 + off);
                ldm_x4_t(fl, stg + 24576 + off);
                mma_bf16(O[2 * gp],     ph[j2], &fh[0]);
                mma_bf16(O[2 * gp],     ph[j2], &fl[0]);
                mma_bf16(O[2 * gp],     pl[j2], &fh[0]);
                mma_bf16(O[2 * gp + 1], ph[j2], &fh[2]);
                mma_bf16(O[2 * gp + 1], ph[j2], &fl[2]);
                mma_bf16(O[2 * gp + 1], pl[j2], &fh[2]);
            }
        }

        __syncthreads();
        if (kt + 2 < SEQ / 64) load_kv(kt & 1, kt + 2);
        CP_COMMIT();
    }

    // ---- epilogue: normalize + split store ----
    const float inv0 = 1.f / l0, inv1 = 1.f / l1;
    const int rg = q0 + w * 16 + (lane >> 2);
    const size_t ob = ((size_t)(b * SEQ)) * D_MODEL + h * DK;
#pragma unroll
    for (int g = 0; g < 8; g++) {
        const int col = g * 8 + (lane & 3) * 2;
        float v0 = O[g][0] * inv0, v1 = O[g][1] * inv0;
        float v2 = O[g][2] * inv1, v3 = O[g][3] * inv1;
        uint32_t h01 = pack_bf16x2(v0, v1);
        uint32_t h23 = pack_bf16x2(v2, v3);
        uint32_t l01 = pack_bf16x2(v0 - __uint_as_float(h01 << 16),
                                   v1 - __uint_as_float(h01 & 0xFFFF0000u));
        uint32_t l23 = pack_bf16x2(v2 - __uint_as_float(h23 << 16),
                                   v3 - __uint_as_float(h23 & 0xFFFF0000u));
        *(uint32_t*)(ctxh + ob + (size_t)rg * D_MODEL + col)       = h01;
        *(uint32_t*)(ctxl + ob + (size_t)rg * D_MODEL + col)       = l01;
        *(uint32_t*)(ctxh + ob + (size_t)(rg + 8) * D_MODEL + col) = h23;
        *(uint32_t*)(ctxl + ob + (size_t)(rg + 8) * D_MODEL + col) = l23;
    }
}

// ---------------- residual add + LayerNorm (optional split output) ---------
template <bool SPLIT>
__launch_bounds__(128)
__global__ void add_ln_kernel(const float* __restrict__ a,
                              const float* __restrict__ r,
                              const float* __restrict__ g,
                              const float* __restrict__ beta,
                              float* __restrict__ out,
                              __nv_bfloat16* __restrict__ oh,
                              __nv_bfloat16* __restrict__ ol)
{
    const int row = blockIdx.x;
    const int tid = threadIdx.x;
    const size_t off = (size_t)row * D_MODEL;
    float v[4];
    float s = 0.f, ss = 0.f;
#pragma unroll
    for (int i = 0; i < 4; i++) {
        int c = tid + i * 128;
        float x = a[off + c] + r[off + c];
        v[i] = x; s += x; ss += x * x;
    }
#pragma unroll
    for (int o = 16; o > 0; o >>= 1) {
        s  += __shfl_xor_sync(0xffffffffu, s, o);
        ss += __shfl_xor_sync(0xffffffffu, ss, o);
    }
    __shared__ float rs[4], rss[4];
    int w = tid >> 5, lane = tid & 31;
    if (lane == 0) { rs[w] = s; rss[w] = ss; }
    __syncthreads();
    s  = rs[0]  + rs[1]  + rs[2]  + rs[3];
    ss = rss[0] + rss[1] + rss[2] + rss[3];
    float mu   = s * (1.f / D_MODEL);
    float var  = ss * (1.f / D_MODEL) - mu * mu;
    float rstd = rsqrtf(var + 1e-5f);
#pragma unroll
    for (int i = 0; i < 4; i++) {
        int c = tid + i * 128;
        float y = (v[i] - mu) * rstd * g[c] + beta[c];
        out[off + c] = y;
        if (SPLIT) {
            __nv_bfloat16 h = __float2bfloat16(y);
            oh[off + c] = h;
            ol[off + c] = __float2bfloat16(y - __bfloat162float(h));
        }
    }
}

// ---------------- launch ---------------------------------------------------
extern "C" void kernel_launch(void* const* d_in, const int* in_sizes, int n_in,
                              void* d_out, int out_size)
{
    (void)in_sizes; (void)n_in; (void)out_size;
    const float* x    = (const float*)d_in[0];
    const int*   mask = (const int*)  d_in[1];
    const float* Wq = (const float*)d_in[2];
    const float* bq = (const float*)d_in[3];
    const float* Wk = (const float*)d_in[4];
    const float* bk = (const float*)d_in[5];
    const float* Wv = (const float*)d_in[6];
    const float* bv = (const float*)d_in[7];
    const float* Wo = (const float*)d_in[8];
    const float* bo = (const float*)d_in[9];
    const float* W1 = (const float*)d_in[10];
    const float* b1 = (const float*)d_in[11];
    const float* W2 = (const float*)d_in[12];
    const float* b2 = (const float*)d_in[13];
    const float* g1 = (const float*)d_in[14];
    const float* be1= (const float*)d_in[15];
    const float* g2 = (const float*)d_in[16];
    const float* be2= (const float*)d_in[17];
    float* out = (float*)d_out;

    float *x1, *tmp;
    __nv_bfloat16 *wh, *wl, *xh, *xl, *qh, *ql, *kh, *kl, *vh, *vl;
    __nv_bfloat16 *ctxh, *ctxl, *x1h, *x1l, *ffh, *ffl;
    cudaGetSymbolAddress((void**)&x1,   g_x1);
    cudaGetSymbolAddress((void**)&tmp,  g_tmp);
    cudaGetSymbolAddress((void**)&wh,   g_wt_h);
    cudaGetSymbolAddress((void**)&wl,   g_wt_l);
    cudaGetSymbolAddress((void**)&xh,   g_xh);
    cudaGetSymbolAddress((void**)&xl,   g_xl);
    cudaGetSymbolAddress((void**)&qh,   g_qh);
    cudaGetSymbolAddress((void**)&ql,   g_ql);
    cudaGetSymbolAddress((void**)&kh,   g_kh);
    cudaGetSymbolAddress((void**)&kl,   g_kl);
    cudaGetSymbolAddress((void**)&vh,   g_vh);
    cudaGetSymbolAddress((void**)&vl,   g_vl);
    cudaGetSymbolAddress((void**)&ctxh, g_ctxh);
    cudaGetSymbolAddress((void**)&ctxl, g_ctxl);
    cudaGetSymbolAddress((void**)&x1h,  g_x1h);
    cudaGetSymbolAddress((void**)&x1l,  g_x1l);
    cudaGetSymbolAddress((void**)&ffh,  g_ffh);
    cudaGetSymbolAddress((void**)&ffl,  g_ffl);

    cudaFuncSetAttribute(sgemm_mma_kernel<false, false>,
                         cudaFuncAttributeMaxDynamicSharedMemorySize, GEMM_SMEM);
    cudaFuncSetAttribute(sgemm_mma_kernel<true, true>,
                         cudaFuncAttributeMaxDynamicSharedMemorySize, GEMM_SMEM);
    cudaFuncSetAttribute(sgemm_mma_kernel<false, true>,
                         cudaFuncAttributeMaxDynamicSharedMemorySize, GEMM_SMEM);
    cudaFuncSetAttribute(attn_mma_kernel,
                         cudaFuncAttributeMaxDynamicSharedMemorySize, ATT_SMEM);

    const int M = NTOK;

    // ---- weight transpose + split; input split ----
    transpose_split_kernel<<<dim3(16, 16), 256>>>(Wq, wh + OFF_WQ, wl + OFF_WQ, 512, 512);
    transpose_split_kernel<<<dim3(16, 16), 256>>>(Wk, wh + OFF_WK, wl + OFF_WK, 512, 512);
    transpose_split_kernel<<<dim3(16, 16), 256>>>(Wv, wh + OFF_WV, wl + OFF_WV, 512, 512);
    transpose_split_kernel<<<dim3(16, 16), 256>>>(Wo, wh + OFF_WO, wl + OFF_WO, 512, 512);
    transpose_split_kernel<<<dim3(64, 16), 256>>>(W1, wh + OFF_W1, wl + OFF_W1, 512, 2048);
    transpose_split_kernel<<<dim3(16, 64), 256>>>(W2, wh + OFF_W2, wl + OFF_W2, 2048, 512);
    split_kernel<<<NTOK * D_MODEL / 256, 256>>>(x, xh, xl);

    // ---- QKV projections -> split bf16 (Q pre-scaled by 0.125*log2e) ----
    {
        dim3 grid(512 / 128, M / 128);
        sgemm_mma_kernel<false, true><<<grid, 256, GEMM_SMEM>>>(
            xh, xl, wh + OFF_WQ, wl + OFF_WQ, bq, nullptr, qh, ql, M, 512, 512, SCALE_Q);
        sgemm_mma_kernel<false, true><<<grid, 256, GEMM_SMEM>>>(
            xh, xl, wh + OFF_WK, wl + OFF_WK, bk, nullptr, kh, kl, M, 512, 512, 1.f);
        sgemm_mma_kernel<false, true><<<grid, 256, GEMM_SMEM>>>(
            xh, xl, wh + OFF_WV, wl + OFF_WV, bv, nullptr, vh, vl, M, 512, 512, 1.f);
    }

    // ---- flash attention (tensor cores) ----
    {
        dim3 grid(SEQ / 128, N_HEADS, BATCH);
        attn_mma_kernel<<<grid, 256, ATT_SMEM>>>(qh, ql, kh, kl, vh, vl, mask, ctxh, ctxl);
    }

    // ---- Wo projection; x1 = LN(x + attn_out) ----
    {
        dim3 grid(512 / 128, M / 128);
        sgemm_mma_kernel<false, false><<<grid, 256, GEMM_SMEM>>>(
            ctxh, ctxl, wh + OFF_WO, wl + OFF_WO, bo, tmp, nullptr, nullptr, M, 512, 512, 1.f);
        add_ln_kernel<true><<<M, 128>>>(x, tmp, g1, be1, x1, x1h, x1l);
    }

    // ---- FF ----
    {
        dim3 grid1(2048 / 128, M / 128);
        sgemm_mma_kernel<true, true><<<grid1, 256, GEMM_SMEM>>>(
            x1h, x1l, wh + OFF_W1, wl + OFF_W1, b1, nullptr, ffh, ffl, M, 2048, 512, 1.f);
        dim3 grid2(512 / 128, M / 128);
        sgemm_mma_kernel<false, false><<<grid2, 256, GEMM_SMEM>>>(
            ffh, ffl, wh + OFF_W2, wl + OFF_W2, b2, tmp, nullptr, nullptr, M, 512, 2048, 1.f);
        add_ln_kernel<false><<<M, 128>>>(x1, tmp, g2, be2, out, nullptr, nullptr);
    }
}

// round 5
// speedup vs baseline: 3.5384x; 1.2412x over previous
#include <cuda_runtime.h>
#include <cuda_bf16.h>
#include <cstdint>
#include <math.h>

#define D_MODEL 512
#define N_HEADS 8
#define DK      64
#define D_FF    2048
#define BATCH   2
#define SEQ     2048
#define NTOK    (BATCH * SEQ)   // 4096

#define SCALE_Q 0.18033688011112042f   // 0.125 * log2(e)

// ---------------- scratch (device globals; no allocation allowed) ----------
static __device__ float g_x1 [(size_t)NTOK * D_MODEL];
static __device__ float g_tmp[(size_t)NTOK * D_MODEL];

static __device__ __nv_bfloat16 g_xh  [(size_t)NTOK * D_MODEL];
static __device__ __nv_bfloat16 g_xl  [(size_t)NTOK * D_MODEL];
static __device__ __nv_bfloat16 g_qh  [(size_t)NTOK * D_MODEL];
static __device__ __nv_bfloat16 g_kh  [(size_t)NTOK * D_MODEL];
static __device__ __nv_bfloat16 g_vh  [(size_t)NTOK * D_MODEL];
static __device__ __nv_bfloat16 g_ctxh[(size_t)NTOK * D_MODEL];
static __device__ __nv_bfloat16 g_ctxl[(size_t)NTOK * D_MODEL];
static __device__ __nv_bfloat16 g_x1h [(size_t)NTOK * D_MODEL];
static __device__ __nv_bfloat16 g_x1l [(size_t)NTOK * D_MODEL];
static __device__ __nv_bfloat16 g_ffh [(size_t)NTOK * D_FF];
static __device__ __nv_bfloat16 g_ffl [(size_t)NTOK * D_FF];

// transposed + hi/lo-split bf16 weights: Wt[n][k]
// WQ/WK/WV contiguous -> fused QKV weight [1536, 512]
#define OFF_WQKV 0
#define OFF_WO   (3*512*512)
#define OFF_W1   (4*512*512)
#define OFF_W2   (4*512*512 + 2048*512)
#define WT_TOTAL (4*512*512 + 2*2048*512)
static __device__ __nv_bfloat16 g_wt_h[WT_TOTAL];
static __device__ __nv_bfloat16 g_wt_l[WT_TOTAL];

// ======================= PTX helpers (base sm_80+ features) ================
__device__ __forceinline__ uint32_t smem_u32(const void* p) {
    uint32_t a;
    asm("{ .reg .u64 t; cvta.to.shared.u64 t, %1; cvt.u32.u64 %0, t; }"
        : "=r"(a) : "l"(p));
    return a;
}
__device__ __forceinline__ void cp_async16(uint32_t dst, const void* src) {
    asm volatile("cp.async.cg.shared.global [%0], [%1], 16;" :: "r"(dst), "l"(src));
}
#define CP_COMMIT() asm volatile("cp.async.commit_group;" ::: "memory")
#define CP_WAIT1()  asm volatile("cp.async.wait_group 1;" ::: "memory")

__device__ __forceinline__ void ldm_x4(uint32_t* r, uint32_t addr) {
    asm volatile("ldmatrix.sync.aligned.m8n8.x4.shared.b16 {%0,%1,%2,%3}, [%4];"
        : "=r"(r[0]), "=r"(r[1]), "=r"(r[2]), "=r"(r[3]) : "r"(addr));
}
__device__ __forceinline__ void ldm_x4_t(uint32_t* r, uint32_t addr) {
    asm volatile("ldmatrix.sync.aligned.m8n8.x4.trans.shared.b16 {%0,%1,%2,%3}, [%4];"
        : "=r"(r[0]), "=r"(r[1]), "=r"(r[2]), "=r"(r[3]) : "r"(addr));
}
__device__ __forceinline__ void mma_bf16(float* c, const uint32_t* a, const uint32_t* b) {
    asm volatile("mma.sync.aligned.m16n8k16.row.col.f32.bf16.bf16.f32 "
        "{%0,%1,%2,%3}, {%4,%5,%6,%7}, {%8,%9}, {%0,%1,%2,%3};"
        : "+f"(c[0]), "+f"(c[1]), "+f"(c[2]), "+f"(c[3])
        : "r"(a[0]), "r"(a[1]), "r"(a[2]), "r"(a[3]), "r"(b[0]), "r"(b[1]));
}
// pack (lo, hi) -> bf16x2 (lo in low half)
__device__ __forceinline__ uint32_t pack_bf16x2(float lo, float hi) {
    uint32_t r;
    asm("cvt.rn.bf16x2.f32 %0, %1, %2;" : "=r"(r) : "f"(hi), "f"(lo));
    return r;
}

// fast exp2 for x <= 0 on the FMA pipe (no MUFU). abs err ~2e-6.
__device__ __forceinline__ float exp2p(float x) {
    x = fmaxf(x, -126.f);
    float t = __fadd_rn(x, 12582912.f);          // round to nearest int
    float n = __fadd_rn(t, -12582912.f);
    float f = x - n;                              // f in [-0.5, 0.5]
    float p = 1.3333558146e-3f;
    p = fmaf(p, f, 9.6181291077e-3f);
    p = fmaf(p, f, 5.5504108665e-2f);
    p = fmaf(p, f, 2.4022650696e-1f);
    p = fmaf(p, f, 6.9314718056e-1f);
    p = fmaf(p, f, 1.0f);
    int e = __float_as_int(t) - 0x4B400000;       // = (int)n
    return p * __int_as_float((e + 127) << 23);
}

// ============ weight transpose + hi/lo bf16 split:  Wt[n][k] = W[k][n] ======
// 4x 512x512 weights (Wq,Wk,Wv,Wo) in one launch via blockIdx.z
__global__ void transpose_split4_kernel(const float* __restrict__ W0,
                                        const float* __restrict__ W1,
                                        const float* __restrict__ W2,
                                        const float* __restrict__ W3,
                                        __nv_bfloat16* __restrict__ Th,
                                        __nv_bfloat16* __restrict__ Tl)
{
    __shared__ float tile[32][33];
    const int z = blockIdx.z;
    const float* W = (z == 0) ? W0 : (z == 1) ? W1 : (z == 2) ? W2 : W3;
    __nv_bfloat16* th = Th + (size_t)z * 512 * 512;
    __nv_bfloat16* tl = Tl + (size_t)z * 512 * 512;
    const int k0 = blockIdx.y * 32, n0 = blockIdx.x * 32;
    const int tx = threadIdx.x & 31, ty = threadIdx.x >> 5;
    for (int i = ty; i < 32; i += 8)
        tile[i][tx] = W[(size_t)(k0 + i) * 512 + n0 + tx];
    __syncthreads();
    for (int i = ty; i < 32; i += 8) {
        float v = tile[tx][i];
        __nv_bfloat16 h = __float2bfloat16(v);
        float lo = v - __bfloat162float(h);
        size_t o = (size_t)(n0 + i) * 512 + k0 + tx;
        th[o] = h;
        tl[o] = __float2bfloat16(lo);
    }
}

__global__ void transpose_split_kernel(const float* __restrict__ W,
                                       __nv_bfloat16* __restrict__ Th,
                                       __nv_bfloat16* __restrict__ Tl,
                                       int K, int N)
{
    __shared__ float tile[32][33];
    const int k0 = blockIdx.y * 32, n0 = blockIdx.x * 32;
    const int tx = threadIdx.x & 31, ty = threadIdx.x >> 5;
    for (int i = ty; i < 32; i += 8)
        tile[i][tx] = W[(size_t)(k0 + i) * N + n0 + tx];
    __syncthreads();
    for (int i = ty; i < 32; i += 8) {
        float v = tile[tx][i];
        __nv_bfloat16 h = __float2bfloat16(v);
        float lo = v - __bfloat162float(h);
        size_t o = (size_t)(n0 + i) * K + k0 + tx;
        Th[o] = h;
        Tl[o] = __float2bfloat16(lo);
    }
}

// ============ elementwise fp32 -> bf16 hi/lo split ==========================
__global__ void split_kernel(const float* __restrict__ X,
                             __nv_bfloat16* __restrict__ Xh,
                             __nv_bfloat16* __restrict__ Xl)
{
    const int i = blockIdx.x * blockDim.x + threadIdx.x;
    float v = X[i];
    __nv_bfloat16 h = __float2bfloat16(v);
    Xh[i] = h;
    Xl[i] = __float2bfloat16(v - __bfloat162float(h));
}

// ================ bf16 tensor-core GEMM: C = A @ B^T + bias ================
// acc = Ah*Bh + Ah*Bl + Al*Bh. Tile 128x128, BK=32, 8 warps, 3-stage cp.async.
// MODE 0: fp32 out (+bias).  MODE 1: split bf16 out (+bias, +relu).
// MODE 2: fused QKV (N=1536): hi-only bf16 out into q/k/v, per-section bias+scale.
#define ROWB 80
#define TILEB (128 * ROWB)
#define GSTAGE (4 * TILEB)        // 40960
#define GEMM_SMEM (3 * GSTAGE)    // 122880

template <int MODE>
__launch_bounds__(256, 1)
__global__ void sgemm_mma_kernel(const __nv_bfloat16* __restrict__ Ah,
                                 const __nv_bfloat16* __restrict__ Al,
                                 const __nv_bfloat16* __restrict__ Bh,
                                 const __nv_bfloat16* __restrict__ Bl,
                                 const float* __restrict__ bias0,
                                 const float* __restrict__ bias1,
                                 const float* __restrict__ bias2,
                                 float* __restrict__ C,
                                 __nv_bfloat16* __restrict__ Ch,
                                 __nv_bfloat16* __restrict__ Cl,
                                 __nv_bfloat16* __restrict__ Qd,
                                 __nv_bfloat16* __restrict__ Kd,
                                 __nv_bfloat16* __restrict__ Vd,
                                 int M, int N, int K)
{
    extern __shared__ char smem[];
    const uint32_t sb = smem_u32(smem);
    const int tid = threadIdx.x;
    const int lane = tid & 31, wid = tid >> 5;
    const int wm = wid & 1, wn = wid >> 1;
    const int bm = blockIdx.y * 128;
    const int bn = blockIdx.x * 128;

    const uint32_t offA = (uint32_t)(wm * 64 + (lane & 15)) * ROWB + (lane >> 4) * 16;
    const uint32_t offB = (uint32_t)(wn * 32 + ((lane & 16) ? 8 : 0) + (lane & 7)) * ROWB
                        + ((lane & 8) ? 16 : 0);

    const __nv_bfloat16* srcBase[4] = {
        Ah + (size_t)bm * K, Al + (size_t)bm * K,
        Bh + (size_t)bn * K, Bl + (size_t)bn * K };

    const int nchunks = K >> 5;

    auto load_stage = [&](int s, int c) {
        const int k0 = c << 5;
        const uint32_t stg = sb + s * GSTAGE;
#pragma unroll
        for (int i = 0; i < 8; i++) {
            int idx = i * 256 + tid;
            int tile = idx >> 9;
            int rem = idx & 511;
            int r = rem >> 2;
            int ch = rem & 3;
            uint32_t dst = stg + tile * TILEB + (uint32_t)r * ROWB + ch * 16;
            cp_async16(dst, srcBase[tile] + (size_t)r * K + k0 + ch * 8);
        }
    };

    float acc[4][4][4];
#pragma unroll
    for (int i = 0; i < 4; i++)
#pragma unroll
        for (int j = 0; j < 4; j++)
#pragma unroll
            for (int t = 0; t < 4; t++) acc[i][j][t] = 0.f;

    load_stage(0, 0); CP_COMMIT();
    load_stage(1, 1); CP_COMMIT();

    int s = 0;
    for (int c = 0; c < nchunks; c++) {
        CP_WAIT1();
        __syncthreads();

        int sw = s + 2; if (sw >= 3) sw -= 3;
        if (c + 2 < nchunks) load_stage(sw, c + 2);
        CP_COMMIT();

        const uint32_t base = sb + s * GSTAGE;
        const uint32_t aH = base + offA;
        const uint32_t aL = aH + TILEB;
        const uint32_t bH = base + 2 * TILEB + offB;
        const uint32_t bL = bH + TILEB;

#pragma unroll
        for (int kst = 0; kst < 2; kst++) {
            const uint32_t kb = kst * 32;
            uint32_t fah[4][4], fal[4][4], fbh[2][4], fbl[2][4];
#pragma unroll
            for (int i = 0; i < 4; i++) {
                ldm_x4(fah[i], aH + i * (16 * ROWB) + kb);
                ldm_x4(fal[i], aL + i * (16 * ROWB) + kb);
            }
#pragma unroll
            for (int jj = 0; jj < 2; jj++) {
                ldm_x4(fbh[jj], bH + jj * (16 * ROWB) + kb);
                ldm_x4(fbl[jj], bL + jj * (16 * ROWB) + kb);
            }
#pragma unroll
            for (int i = 0; i < 4; i++)
#pragma unroll
                for (int j = 0; j < 4; j++) {
                    const uint32_t* bhp = &fbh[j >> 1][(j & 1) * 2];
                    const uint32_t* blp = &fbl[j >> 1][(j & 1) * 2];
                    mma_bf16(acc[i][j], fah[i], bhp);
                    mma_bf16(acc[i][j], fah[i], blp);
                    mma_bf16(acc[i][j], fal[i], bhp);
                }
        }
        if (++s == 3) s = 0;
    }

    // -------- epilogue --------
    const int tr = lane >> 2;
    const int tc2 = (lane & 3) * 2;

    // MODE 2: section select (tile never crosses a 512 boundary since bn%128==0)
    const float* biasS = bias0;
    __nv_bfloat16* dstS = Qd;
    float scaleS = 1.f;
    if (MODE == 2) {
        const int sec = bn >> 9;
        biasS  = (sec == 0) ? bias0 : (sec == 1) ? bias1 : bias2;
        dstS   = (sec == 0) ? Qd : (sec == 1) ? Kd : Vd;
        scaleS = (sec == 0) ? SCALE_Q : 1.f;
    }

#pragma unroll
    for (int i = 0; i < 4; i++) {
#pragma unroll
        for (int j = 0; j < 4; j++) {
            const int r = bm + wm * 64 + i * 16 + tr;
            const int ncol = bn + wn * 32 + j * 8 + tc2;
#pragma unroll
            for (int half = 0; half < 2; half++) {
                float v0 = acc[i][j][half * 2 + 0];
                float v1 = acc[i][j][half * 2 + 1];
                const size_t row = (size_t)(r + half * 8);
                if (MODE == 0) {
                    v0 += bias0[ncol]; v1 += bias0[ncol + 1];
                    *(float2*)(C + row * N + ncol) = make_float2(v0, v1);
                } else if (MODE == 1) {
                    v0 += bias0[ncol]; v1 += bias0[ncol + 1];
                    v0 = fmaxf(v0, 0.f); v1 = fmaxf(v1, 0.f);
                    __nv_bfloat16 h0 = __float2bfloat16(v0);
                    __nv_bfloat16 h1 = __float2bfloat16(v1);
                    __nv_bfloat162 hh; hh.x = h0; hh.y = h1;
                    __nv_bfloat162 ll;
                    ll.x = __float2bfloat16(v0 - __bfloat162float(h0));
                    ll.y = __float2bfloat16(v1 - __bfloat162float(h1));
                    *(__nv_bfloat162*)(Ch + row * N + ncol) = hh;
                    *(__nv_bfloat162*)(Cl + row * N + ncol) = ll;
                } else {
                    const int col = ncol & 511;
                    v0 = (v0 + biasS[col]) * scaleS;
                    v1 = (v1 + biasS[col + 1]) * scaleS;
                    *(uint32_t*)(dstS + row * 512 + col) = pack_bf16x2(v0, v1);
                }
            }
        }
    }
}

// ================== tensor-core flash attention (plain bf16) ================
// 128 q-rows per CTA, 8 warps (16 rows each), kv tiles of 64 tokens.
// Q pre-scaled by 0.125*log2e; softmax in base-2 with poly exp2 (FMA pipe).
// smem: madd[2048]f (8KB) | Qh 16KB | 2 stages x (kh 8KB + vh 8KB)
#define ATT_SMEM (8192 + 16384 + 2 * 16384)   // 57344

__launch_bounds__(256, 1)
__global__ void attn_mma_kernel(const __nv_bfloat16* __restrict__ qh,
                                const __nv_bfloat16* __restrict__ kh,
                                const __nv_bfloat16* __restrict__ vh,
                                const int* __restrict__ mask,
                                __nv_bfloat16* __restrict__ ctxh,
                                __nv_bfloat16* __restrict__ ctxl)
{
    extern __shared__ char smc[];
    const uint32_t sb = smem_u32(smc);
    const int tid = threadIdx.x, lane = tid & 31, w = tid >> 5;
    const int qt = blockIdx.x, h = blockIdx.y, b = blockIdx.z;
    const int q0 = qt * 128;
    const size_t qbase  = ((size_t)(b * SEQ + q0)) * D_MODEL + h * DK;
    const size_t kvbase = ((size_t)(b * SEQ)) * D_MODEL + h * DK;

    float* madd = (float*)smc;
    for (int i = tid; i < SEQ; i += 256)
        madd[i] = (mask[b * SEQ + i] == 0) ? -1e9f : 0.f;

    auto load_kv = [&](int stg_i, int ktile) {
        const uint32_t stg = sb + 24576 + stg_i * 16384;
        const size_t tokbase = kvbase + (size_t)ktile * 64 * D_MODEL;
        const __nv_bfloat16* srcs[2] = { kh + tokbase, vh + tokbase };
#pragma unroll
        for (int i = 0; i < 4; i++) {
            int idx = i * 256 + tid;
            int t2 = idx >> 9;
            int rem = idx & 511;
            int r = rem >> 3, c = rem & 7;
            uint32_t off = (uint32_t)r * 128 + (uint32_t)((c ^ (r & 7)) << 4);
            cp_async16(stg + t2 * 8192 + off, srcs[t2] + (size_t)r * D_MODEL + c * 8);
        }
    };

    // prologue: Q + stage0, stage1
#pragma unroll
    for (int i = 0; i < 4; i++) {
        int idx = i * 256 + tid;
        int r = idx >> 3, c = idx & 7;
        uint32_t off = (uint32_t)r * 128 + (uint32_t)((c ^ (r & 7)) << 4);
        cp_async16(sb + 8192 + off, qh + qbase + (size_t)r * D_MODEL + c * 8);
    }
    load_kv(0, 0);
    CP_COMMIT();
    load_kv(1, 1);
    CP_COMMIT();

    CP_WAIT1();
    __syncthreads();

    // Q fragments (registers for whole kernel)
    uint32_t qfh[4][4];
    {
        const uint32_t qrow = (uint32_t)(w * 16 + (lane & 15));
        const uint32_t qc = (uint32_t)(lane >> 4);
#pragma unroll
        for (int ks = 0; ks < 4; ks++) {
            uint32_t c16 = ks * 2 + qc;
            uint32_t off = qrow * 128 + ((c16 ^ (qrow & 7)) << 4);
            ldm_x4(qfh[ks], sb + 8192 + off);
        }
    }

    float m0 = -1e30f, m1 = -1e30f, l0 = 0.f, l1 = 0.f;
    float O[8][4];
#pragma unroll
    for (int g = 0; g < 8; g++)
#pragma unroll
        for (int t = 0; t < 4; t++) O[g][t] = 0.f;

    const uint32_t kr_base = (uint32_t)(((lane & 16) ? 8 : 0) + (lane & 7));
    const uint32_t kc_add  = (uint32_t)((lane & 8) ? 1 : 0);
    const uint32_t vr_base = (uint32_t)(lane & 15);
    const uint32_t vc_add  = (uint32_t)(lane >> 4);

    for (int kt = 0; kt < SEQ / 64; kt++) {
        if (kt > 0) { CP_WAIT1(); __syncthreads(); }
        const uint32_t stg = sb + 24576 + (kt & 1) * 16384;

        // ---- S = Q @ K^T ----
        float S[8][4];
#pragma unroll
        for (int g = 0; g < 8; g++)
#pragma unroll
            for (int t = 0; t < 4; t++) S[g][t] = 0.f;

#pragma unroll
        for (int tg = 0; tg < 4; tg++) {
            const uint32_t row = tg * 16 + kr_base;
#pragma unroll
            for (int ks = 0; ks < 4; ks++) {
                uint32_t c16 = ks * 2 + kc_add;
                uint32_t off = row * 128 + ((c16 ^ (row & 7)) << 4);
                uint32_t fh[4];
                ldm_x4(fh, stg + off);
                mma_bf16(S[2 * tg],     qfh[ks], &fh[0]);
                mma_bf16(S[2 * tg + 1], qfh[ks], &fh[2]);
            }
        }

        // ---- mask + online softmax (base 2) ----
        float mt0 = -1e30f, mt1 = -1e30f;
#pragma unroll
        for (int g = 0; g < 8; g++) {
            float2 ma = *(float2*)&madd[kt * 64 + g * 8 + (lane & 3) * 2];
            S[g][0] += ma.x; S[g][1] += ma.y;
            S[g][2] += ma.x; S[g][3] += ma.y;
            mt0 = fmaxf(mt0, fmaxf(S[g][0], S[g][1]));
            mt1 = fmaxf(mt1, fmaxf(S[g][2], S[g][3]));
        }
        mt0 = fmaxf(mt0, __shfl_xor_sync(0xffffffffu, mt0, 1));
        mt0 = fmaxf(mt0, __shfl_xor_sync(0xffffffffu, mt0, 2));
        mt1 = fmaxf(mt1, __shfl_xor_sync(0xffffffffu, mt1, 1));
        mt1 = fmaxf(mt1, __shfl_xor_sync(0xffffffffu, mt1, 2));

        const float mn0 = fmaxf(m0, mt0), mn1 = fmaxf(m1, mt1);
        const float a0 = exp2p(m0 - mn0), a1 = exp2p(m1 - mn1);
        m0 = mn0; m1 = mn1;

        float s0 = 0.f, s1 = 0.f;
        uint32_t ph[4][4];
#pragma unroll
        for (int g = 0; g < 8; g++) {
            float p0 = exp2p(S[g][0] - m0);
            float p1 = exp2p(S[g][1] - m0);
            float p2 = exp2p(S[g][2] - m1);
            float p3 = exp2p(S[g][3] - m1);
            s0 += p0 + p1; s1 += p2 + p3;
            ph[g >> 1][(g & 1) * 2 + 0] = pack_bf16x2(p0, p1);
            ph[g >> 1][(g & 1) * 2 + 1] = pack_bf16x2(p2, p3);
        }
        s0 += __shfl_xor_sync(0xffffffffu, s0, 1);
        s0 += __shfl_xor_sync(0xffffffffu, s0, 2);
        s1 += __shfl_xor_sync(0xffffffffu, s1, 1);
        s1 += __shfl_xor_sync(0xffffffffu, s1, 2);
        l0 = l0 * a0 + s0;
        l1 = l1 * a1 + s1;

#pragma unroll
        for (int g = 0; g < 8; g++) {
            O[g][0] *= a0; O[g][1] *= a0;
            O[g][2] *= a1; O[g][3] *= a1;
        }

        // ---- O += P @ V ----
#pragma unroll
        for (int gp = 0; gp < 4; gp++) {
#pragma unroll
            for (int j2 = 0; j2 < 4; j2++) {
                uint32_t row = j2 * 16 + vr_base;
                uint32_t c16 = gp * 2 + vc_add;
                uint32_t off = row * 128 + ((c16 ^ (row & 7)) << 4);
                uint32_t fh[4];
                ldm_x4_t(fh, stg + 8192 + off);
                mma_bf16(O[2 * gp],     ph[j2], &fh[0]);
                mma_bf16(O[2 * gp + 1], ph[j2], &fh[2]);
            }
        }

        __syncthreads();
        if (kt + 2 < SEQ / 64) load_kv(kt & 1, kt + 2);
        CP_COMMIT();
    }

    // ---- epilogue: normalize + split store (ctx feeds 3-product Wo GEMM) ----
    const float inv0 = 1.f / l0, inv1 = 1.f / l1;
    const int rg = q0 + w * 16 + (lane >> 2);
    const size_t ob = ((size_t)(b * SEQ)) * D_MODEL + h * DK;
#pragma unroll
    for (int g = 0; g < 8; g++) {
        const int col = g * 8 + (lane & 3) * 2;
        float v0 = O[g][0] * inv0, v1 = O[g][1] * inv0;
        float v2 = O[g][2] * inv1, v3 = O[g][3] * inv1;
        uint32_t h01 = pack_bf16x2(v0, v1);
        uint32_t h23 = pack_bf16x2(v2, v3);
        uint32_t l01 = pack_bf16x2(v0 - __uint_as_float(h01 << 16),
                                   v1 - __uint_as_float(h01 & 0xFFFF0000u));
        uint32_t l23 = pack_bf16x2(v2 - __uint_as_float(h23 << 16),
                                   v3 - __uint_as_float(h23 & 0xFFFF0000u));
        *(uint32_t*)(ctxh + ob + (size_t)rg * D_MODEL + col)       = h01;
        *(uint32_t*)(ctxl + ob + (size_t)rg * D_MODEL + col)       = l01;
        *(uint32_t*)(ctxh + ob + (size_t)(rg + 8) * D_MODEL + col) = h23;
        *(uint32_t*)(ctxl + ob + (size_t)(rg + 8) * D_MODEL + col) = l23;
    }
}

// ---------------- residual add + LayerNorm (optional split output) ---------
template <bool SPLIT>
__launch_bounds__(128)
__global__ void add_ln_kernel(const float* __restrict__ a,
                              const float* __restrict__ r,
                              const float* __restrict__ g,
                              const float* __restrict__ beta,
                              float* __restrict__ out,
                              __nv_bfloat16* __restrict__ oh,
                              __nv_bfloat16* __restrict__ ol)
{
    const int row = blockIdx.x;
    const int tid = threadIdx.x;
    const size_t off = (size_t)row * D_MODEL;
    float v[4];
    float s = 0.f, ss = 0.f;
#pragma unroll
    for (int i = 0; i < 4; i++) {
        int c = tid + i * 128;
        float x = a[off + c] + r[off + c];
        v[i] = x; s += x; ss += x * x;
    }
#pragma unroll
    for (int o = 16; o > 0; o >>= 1) {
        s  += __shfl_xor_sync(0xffffffffu, s, o);
        ss += __shfl_xor_sync(0xffffffffu, ss, o);
    }
    __shared__ float rs[4], rss[4];
    int w = tid >> 5, lane = tid & 31;
    if (lane == 0) { rs[w] = s; rss[w] = ss; }
    __syncthreads();
    s  = rs[0]  + rs[1]  + rs[2]  + rs[3];
    ss = rss[0] + rss[1] + rss[2] + rss[3];
    float mu   = s * (1.f / D_MODEL);
    float var  = ss * (1.f / D_MODEL) - mu * mu;
    float rstd = rsqrtf(var + 1e-5f);
#pragma unroll
    for (int i = 0; i < 4; i++) {
        int c = tid + i * 128;
        float y = (v[i] - mu) * rstd * g[c] + beta[c];
        out[off + c] = y;
        if (SPLIT) {
            __nv_bfloat16 h = __float2bfloat16(y);
            oh[off + c] = h;
            ol[off + c] = __float2bfloat16(y - __bfloat162float(h));
        }
    }
}

// ---------------- launch ---------------------------------------------------
extern "C" void kernel_launch(void* const* d_in, const int* in_sizes, int n_in,
                              void* d_out, int out_size)
{
    (void)in_sizes; (void)n_in; (void)out_size;
    const float* x    = (const float*)d_in[0];
    const int*   mask = (const int*)  d_in[1];
    const float* Wq = (const float*)d_in[2];
    const float* bq = (const float*)d_in[3];
    const float* Wk = (const float*)d_in[4];
    const float* bk = (const float*)d_in[5];
    const float* Wv = (const float*)d_in[6];
    const float* bv = (const float*)d_in[7];
    const float* Wo = (const float*)d_in[8];
    const float* bo = (const float*)d_in[9];
    const float* W1 = (const float*)d_in[10];
    const float* b1 = (const float*)d_in[11];
    const float* W2 = (const float*)d_in[12];
    const float* b2 = (const float*)d_in[13];
    const float* g1 = (const float*)d_in[14];
    const float* be1= (const float*)d_in[15];
    const float* g2 = (const float*)d_in[16];
    const float* be2= (const float*)d_in[17];
    float* out = (float*)d_out;

    float *x1, *tmp;
    __nv_bfloat16 *wh, *wl, *xh, *xl, *qh, *kh, *vh;
    __nv_bfloat16 *ctxh, *ctxl, *x1h, *x1l, *ffh, *ffl;
    cudaGetSymbolAddress((void**)&x1,   g_x1);
    cudaGetSymbolAddress((void**)&tmp,  g_tmp);
    cudaGetSymbolAddress((void**)&wh,   g_wt_h);
    cudaGetSymbolAddress((void**)&wl,   g_wt_l);
    cudaGetSymbolAddress((void**)&xh,   g_xh);
    cudaGetSymbolAddress((void**)&xl,   g_xl);
    cudaGetSymbolAddress((void**)&qh,   g_qh);
    cudaGetSymbolAddress((void**)&kh,   g_kh);
    cudaGetSymbolAddress((void**)&vh,   g_vh);
    cudaGetSymbolAddress((void**)&ctxh, g_ctxh);
    cudaGetSymbolAddress((void**)&ctxl, g_ctxl);
    cudaGetSymbolAddress((void**)&x1h,  g_x1h);
    cudaGetSymbolAddress((void**)&x1l,  g_x1l);
    cudaGetSymbolAddress((void**)&ffh,  g_ffh);
    cudaGetSymbolAddress((void**)&ffl,  g_ffl);

    cudaFuncSetAttribute(sgemm_mma_kernel<0>,
                         cudaFuncAttributeMaxDynamicSharedMemorySize, GEMM_SMEM);
    cudaFuncSetAttribute(sgemm_mma_kernel<1>,
                         cudaFuncAttributeMaxDynamicSharedMemorySize, GEMM_SMEM);
    cudaFuncSetAttribute(sgemm_mma_kernel<2>,
                         cudaFuncAttributeMaxDynamicSharedMemorySize, GEMM_SMEM);
    cudaFuncSetAttribute(attn_mma_kernel,
                         cudaFuncAttributeMaxDynamicSharedMemorySize, ATT_SMEM);

    const int M = NTOK;

    // 0: Wq/Wk/Wv (-> fused QKV region) + Wo transpose+split
    transpose_split4_kernel<<<dim3(16, 16, 4), 256>>>(Wq, Wk, Wv, Wo, wh, wl);
    // 1: W1, 2: W2
    transpose_split_kernel<<<dim3(64, 16), 256>>>(W1, wh + OFF_W1, wl + OFF_W1, 512, 2048);
    transpose_split_kernel<<<dim3(16, 64), 256>>>(W2, wh + OFF_W2, wl + OFF_W2, 2048, 512);
    // 3: x split
    split_kernel<<<NTOK * D_MODEL / 256, 256>>>(x, xh, xl);

    // 4: fused QKV projection (hi-only bf16 out, Q pre-scaled)
    {
        dim3 grid(1536 / 128, M / 128);
        sgemm_mma_kernel<2><<<grid, 256, GEMM_SMEM>>>(
            xh, xl, wh + OFF_WQKV, wl + OFF_WQKV, bq, bk, bv,
            nullptr, nullptr, nullptr, qh, kh, vh, M, 1536, 512);
    }

    // 5: flash attention (plain bf16 tensor cores)
    {
        dim3 grid(SEQ / 128, N_HEADS, BATCH);
        attn_mma_kernel<<<grid, 256, ATT_SMEM>>>(qh, kh, vh, mask, ctxh, ctxl);
    }

    // 6-7: Wo projection; x1 = LN(x + attn_out)
    {
        dim3 grid(512 / 128, M / 128);
        sgemm_mma_kernel<0><<<grid, 256, GEMM_SMEM>>>(
            ctxh, ctxl, wh + OFF_WO, wl + OFF_WO, bo, nullptr, nullptr,
            tmp, nullptr, nullptr, nullptr, nullptr, nullptr, M, 512, 512);
        add_ln_kernel<true><<<M, 128>>>(x, tmp, g1, be1, x1, x1h, x1l);
    }

    // 8-10: FF
    {
        dim3 grid1(2048 / 128, M / 128);
        sgemm_mma_kernel<1><<<grid1, 256, GEMM_SMEM>>>(
            x1h, x1l, wh + OFF_W1, wl + OFF_W1, b1, nullptr, nullptr,
            nullptr, ffh, ffl, nullptr, nullptr, nullptr, M, 2048, 512);
        dim3 grid2(512 / 128, M / 128);
        sgemm_mma_kernel<0><<<grid2, 256, GEMM_SMEM>>>(
            ffh, ffl, wh + OFF_W2, wl + OFF_W2, b2, nullptr, nullptr,
            tmp, nullptr, nullptr, nullptr, nullptr, nullptr, M, 512, 2048);
        add_ln_kernel<false><<<M, 128>>>(x1, tmp, g2, be2, out, nullptr, nullptr);
    }
}

// round 6
// speedup vs baseline: 6.1709x; 1.7440x over previous
#include <cuda_runtime.h>
#include <cuda_fp16.h>
#include <cstdint>
#include <math.h>

#define D_MODEL 512
#define N_HEADS 8
#define DK      64
#define D_FF    2048
#define BATCH   2
#define SEQ     2048
#define NTOK    (BATCH * SEQ)   // 4096

#define SCALE_Q 0.18033688011112042f   // 0.125 * log2(e)

// ---------------- scratch (device globals; no allocation allowed) ----------
static __device__ float g_x1 [(size_t)NTOK * D_MODEL];
static __device__ float g_tmp[(size_t)NTOK * D_MODEL];

static __device__ __half g_xh [(size_t)NTOK * D_MODEL];
static __device__ __half g_qh [(size_t)NTOK * D_MODEL];
static __device__ __half g_kh [(size_t)NTOK * D_MODEL];
static __device__ __half g_vh [(size_t)NTOK * D_MODEL];
static __device__ __half g_ctx[(size_t)NTOK * D_MODEL];
static __device__ __half g_x1h[(size_t)NTOK * D_MODEL];
static __device__ __half g_ffh[(size_t)NTOK * D_FF];

// transposed fp16 weights: Wt[n][k]; WQ/WK/WV contiguous -> fused [1536,512]
#define OFF_WQKV 0
#define OFF_WO   (3*512*512)
#define OFF_W1   (4*512*512)
#define OFF_W2   (4*512*512 + 2048*512)
#define WT_TOTAL (4*512*512 + 2*2048*512)
static __device__ __half g_wt[WT_TOTAL];

// ======================= PTX helpers (base sm_80+ features) ================
__device__ __forceinline__ uint32_t smem_u32(const void* p) {
    uint32_t a;
    asm("{ .reg .u64 t; cvta.to.shared.u64 t, %1; cvt.u32.u64 %0, t; }"
        : "=r"(a) : "l"(p));
    return a;
}
__device__ __forceinline__ void cp_async16(uint32_t dst, const void* src) {
    asm volatile("cp.async.cg.shared.global [%0], [%1], 16;" :: "r"(dst), "l"(src));
}
#define CP_COMMIT() asm volatile("cp.async.commit_group;" ::: "memory")
#define CP_WAIT1()  asm volatile("cp.async.wait_group 1;" ::: "memory")

__device__ __forceinline__ void ldm_x4(uint32_t* r, uint32_t addr) {
    asm volatile("ldmatrix.sync.aligned.m8n8.x4.shared.b16 {%0,%1,%2,%3}, [%4];"
        : "=r"(r[0]), "=r"(r[1]), "=r"(r[2]), "=r"(r[3]) : "r"(addr));
}
__device__ __forceinline__ void ldm_x4_t(uint32_t* r, uint32_t addr) {
    asm volatile("ldmatrix.sync.aligned.m8n8.x4.trans.shared.b16 {%0,%1,%2,%3}, [%4];"
        : "=r"(r[0]), "=r"(r[1]), "=r"(r[2]), "=r"(r[3]) : "r"(addr));
}
__device__ __forceinline__ void mma_f16(float* c, const uint32_t* a, const uint32_t* b) {
    asm volatile("mma.sync.aligned.m16n8k16.row.col.f32.f16.f16.f32 "
        "{%0,%1,%2,%3}, {%4,%5,%6,%7}, {%8,%9}, {%0,%1,%2,%3};"
        : "+f"(c[0]), "+f"(c[1]), "+f"(c[2]), "+f"(c[3])
        : "r"(a[0]), "r"(a[1]), "r"(a[2]), "r"(a[3]), "r"(b[0]), "r"(b[1]));
}
// pack (lo, hi) -> f16x2 (lo in low half)
__device__ __forceinline__ uint32_t pack_f16x2(float lo, float hi) {
    uint32_t r;
    asm("cvt.rn.f16x2.f32 %0, %1, %2;" : "=r"(r) : "f"(hi), "f"(lo));
    return r;
}

// fast exp2 for x <= 0 on the FMA pipe (no MUFU). abs err ~2e-6.
__device__ __forceinline__ float exp2p(float x) {
    x = fmaxf(x, -126.f);
    float t = __fadd_rn(x, 12582912.f);          // round to nearest int
    float n = __fadd_rn(t, -12582912.f);
    float f = x - n;                              // f in [-0.5, 0.5]
    float p = 1.3333558146e-3f;
    p = fmaf(p, f, 9.6181291077e-3f);
    p = fmaf(p, f, 5.5504108665e-2f);
    p = fmaf(p, f, 2.4022650696e-1f);
    p = fmaf(p, f, 6.9314718056e-1f);
    p = fmaf(p, f, 1.0f);
    int e = __float_as_int(t) - 0x4B400000;       // = (int)n
    return p * __int_as_float((e + 127) << 23);
}

// ============ weight transpose to fp16:  Wt[n][k] = W[k][n] =================
// 4x 512x512 weights (Wq,Wk,Wv,Wo) in one launch via blockIdx.z
__global__ void transpose4_kernel(const float* __restrict__ W0,
                                  const float* __restrict__ W1,
                                  const float* __restrict__ W2,
                                  const float* __restrict__ W3,
                                  __half* __restrict__ T)
{
    __shared__ float tile[32][33];
    const int z = blockIdx.z;
    const float* W = (z == 0) ? W0 : (z == 1) ? W1 : (z == 2) ? W2 : W3;
    __half* t = T + (size_t)z * 512 * 512;
    const int k0 = blockIdx.y * 32, n0 = blockIdx.x * 32;
    const int tx = threadIdx.x & 31, ty = threadIdx.x >> 5;
    for (int i = ty; i < 32; i += 8)
        tile[i][tx] = W[(size_t)(k0 + i) * 512 + n0 + tx];
    __syncthreads();
    for (int i = ty; i < 32; i += 8)
        t[(size_t)(n0 + i) * 512 + k0 + tx] = __float2half(tile[tx][i]);
}

__global__ void transpose_kernel(const float* __restrict__ W,
                                 __half* __restrict__ T, int K, int N)
{
    __shared__ float tile[32][33];
    const int k0 = blockIdx.y * 32, n0 = blockIdx.x * 32;
    const int tx = threadIdx.x & 31, ty = threadIdx.x >> 5;
    for (int i = ty; i < 32; i += 8)
        tile[i][tx] = W[(size_t)(k0 + i) * N + n0 + tx];
    __syncthreads();
    for (int i = ty; i < 32; i += 8)
        T[(size_t)(n0 + i) * K + k0 + tx] = __float2half(tile[tx][i]);
}

// ============ elementwise fp32 -> fp16 ======================================
__global__ void cvt_kernel(const float* __restrict__ X, __half* __restrict__ Xh)
{
    const int i = (blockIdx.x * blockDim.x + threadIdx.x) * 4;
    float4 v = *(const float4*)(X + i);
    uint32_t lo = pack_f16x2(v.x, v.y);
    uint32_t hi = pack_f16x2(v.z, v.w);
    *(uint2*)(Xh + i) = make_uint2(lo, hi);
}

// ================ fp16 tensor-core GEMM: C = A @ B^T + bias =================
// A fp16 [M,K] row-major; B fp16 [N,K] K-major. fp32 accumulate.
// Tile 128x128, BK=32, 8 warps (64x32 warp tile), 3-stage cp.async.
// MODE 0: fp32 out (+bias).  MODE 1: fp16 out (+bias, +relu).
// MODE 2: fused QKV (N=1536): fp16 out into q/k/v, per-section bias+scale.
#define ROWB 80
#define TILEB (128 * ROWB)        // 10240
#define GSTAGE (2 * TILEB)        // 20480
#define GEMM_SMEM (3 * GSTAGE)    // 61440

template <int MODE>
__launch_bounds__(256)
__global__ void sgemm_mma_kernel(const __half* __restrict__ A,
                                 const __half* __restrict__ B,
                                 const float* __restrict__ bias0,
                                 const float* __restrict__ bias1,
                                 const float* __restrict__ bias2,
                                 float* __restrict__ C,
                                 __half* __restrict__ Ch,
                                 __half* __restrict__ Qd,
                                 __half* __restrict__ Kd,
                                 __half* __restrict__ Vd,
                                 int M, int N, int K)
{
    extern __shared__ char smem[];
    const uint32_t sb = smem_u32(smem);
    const int tid = threadIdx.x;
    const int lane = tid & 31, wid = tid >> 5;
    const int wm = wid & 1, wn = wid >> 1;
    const int bm = blockIdx.y * 128;
    const int bn = blockIdx.x * 128;

    const uint32_t offA = (uint32_t)(wm * 64 + (lane & 15)) * ROWB + (lane >> 4) * 16;
    const uint32_t offB = (uint32_t)(wn * 32 + ((lane & 16) ? 8 : 0) + (lane & 7)) * ROWB
                        + ((lane & 8) ? 16 : 0);

    const __half* srcBase[2] = { A + (size_t)bm * K, B + (size_t)bn * K };

    const int nchunks = K >> 5;

    auto load_stage = [&](int s, int c) {
        const int k0 = c << 5;
        const uint32_t stg = sb + s * GSTAGE;
#pragma unroll
        for (int i = 0; i < 4; i++) {
            int idx = i * 256 + tid;
            int tile = idx >> 9;
            int rem = idx & 511;
            int r = rem >> 2;
            int ch = rem & 3;
            uint32_t dst = stg + tile * TILEB + (uint32_t)r * ROWB + ch * 16;
            cp_async16(dst, srcBase[tile] + (size_t)r * K + k0 + ch * 8);
        }
    };

    float acc[4][4][4];
#pragma unroll
    for (int i = 0; i < 4; i++)
#pragma unroll
        for (int j = 0; j < 4; j++)
#pragma unroll
            for (int t = 0; t < 4; t++) acc[i][j][t] = 0.f;

    load_stage(0, 0); CP_COMMIT();
    load_stage(1, 1); CP_COMMIT();

    int s = 0;
    for (int c = 0; c < nchunks; c++) {
        CP_WAIT1();
        __syncthreads();

        int sw = s + 2; if (sw >= 3) sw -= 3;
        if (c + 2 < nchunks) load_stage(sw, c + 2);
        CP_COMMIT();

        const uint32_t base = sb + s * GSTAGE;
        const uint32_t aP = base + offA;
        const uint32_t bP = base + TILEB + offB;

#pragma unroll
        for (int kst = 0; kst < 2; kst++) {
            const uint32_t kb = kst * 32;
            uint32_t fa[4][4], fb[2][4];
#pragma unroll
            for (int i = 0; i < 4; i++)
                ldm_x4(fa[i], aP + i * (16 * ROWB) + kb);
#pragma unroll
            for (int jj = 0; jj < 2; jj++)
                ldm_x4(fb[jj], bP + jj * (16 * ROWB) + kb);
#pragma unroll
            for (int i = 0; i < 4; i++)
#pragma unroll
                for (int j = 0; j < 4; j++)
                    mma_f16(acc[i][j], fa[i], &fb[j >> 1][(j & 1) * 2]);
        }
        if (++s == 3) s = 0;
    }

    // -------- epilogue --------
    const int tr = lane >> 2;
    const int tc2 = (lane & 3) * 2;

    const float* biasS = bias0;
    __half* dstS = Qd;
    float scaleS = 1.f;
    if (MODE == 2) {
        const int sec = bn >> 9;
        biasS  = (sec == 0) ? bias0 : (sec == 1) ? bias1 : bias2;
        dstS   = (sec == 0) ? Qd : (sec == 1) ? Kd : Vd;
        scaleS = (sec == 0) ? SCALE_Q : 1.f;
    }

#pragma unroll
    for (int i = 0; i < 4; i++) {
#pragma unroll
        for (int j = 0; j < 4; j++) {
            const int r = bm + wm * 64 + i * 16 + tr;
            const int ncol = bn + wn * 32 + j * 8 + tc2;
#pragma unroll
            for (int half = 0; half < 2; half++) {
                float v0 = acc[i][j][half * 2 + 0];
                float v1 = acc[i][j][half * 2 + 1];
                const size_t row = (size_t)(r + half * 8);
                if (MODE == 0) {
                    v0 += bias0[ncol]; v1 += bias0[ncol + 1];
                    *(float2*)(C + row * N + ncol) = make_float2(v0, v1);
                } else if (MODE == 1) {
                    v0 = fmaxf(v0 + bias0[ncol], 0.f);
                    v1 = fmaxf(v1 + bias0[ncol + 1], 0.f);
                    *(uint32_t*)(Ch + row * N + ncol) = pack_f16x2(v0, v1);
                } else {
                    const int col = ncol & 511;
                    v0 = (v0 + biasS[col]) * scaleS;
                    v1 = (v1 + biasS[col + 1]) * scaleS;
                    *(uint32_t*)(dstS + row * 512 + col) = pack_f16x2(v0, v1);
                }
            }
        }
    }
}

// ================== tensor-core flash attention (fp16) ======================
// 128 q-rows per CTA, 8 warps (16 rows each), kv tiles of 64 tokens.
// Q pre-scaled by 0.125*log2e; softmax in base-2 with poly exp2 (FMA pipe).
// smem: madd[2048]f (8KB) | Q 16KB | 2 stages x (k 8KB + v 8KB)
#define ATT_SMEM (8192 + 16384 + 2 * 16384)   // 57344

__launch_bounds__(256)
__global__ void attn_mma_kernel(const __half* __restrict__ qh,
                                const __half* __restrict__ kh,
                                const __half* __restrict__ vh,
                                const int* __restrict__ mask,
                                __half* __restrict__ ctx)
{
    extern __shared__ char smc[];
    const uint32_t sb = smem_u32(smc);
    const int tid = threadIdx.x, lane = tid & 31, w = tid >> 5;
    const int qt = blockIdx.x, h = blockIdx.y, b = blockIdx.z;
    const int q0 = qt * 128;
    const size_t qbase  = ((size_t)(b * SEQ + q0)) * D_MODEL + h * DK;
    const size_t kvbase = ((size_t)(b * SEQ)) * D_MODEL + h * DK;

    float* madd = (float*)smc;
    for (int i = tid; i < SEQ; i += 256)
        madd[i] = (mask[b * SEQ + i] == 0) ? -1e9f : 0.f;

    auto load_kv = [&](int stg_i, int ktile) {
        const uint32_t stg = sb + 24576 + stg_i * 16384;
        const size_t tokbase = kvbase + (size_t)ktile * 64 * D_MODEL;
        const __half* srcs[2] = { kh + tokbase, vh + tokbase };
#pragma unroll
        for (int i = 0; i < 4; i++) {
            int idx = i * 256 + tid;
            int t2 = idx >> 9;
            int rem = idx & 511;
            int r = rem >> 3, c = rem & 7;
            uint32_t off = (uint32_t)r * 128 + (uint32_t)((c ^ (r & 7)) << 4);
            cp_async16(stg + t2 * 8192 + off, srcs[t2] + (size_t)r * D_MODEL + c * 8);
        }
    };

    // prologue: Q + stage0, stage1
#pragma unroll
    for (int i = 0; i < 4; i++) {
        int idx = i * 256 + tid;
        int r = idx >> 3, c = idx & 7;
        uint32_t off = (uint32_t)r * 128 + (uint32_t)((c ^ (r & 7)) << 4);
        cp_async16(sb + 8192 + off, qh + qbase + (size_t)r * D_MODEL + c * 8);
    }
    load_kv(0, 0);
    CP_COMMIT();
    load_kv(1, 1);
    CP_COMMIT();

    CP_WAIT1();
    __syncthreads();

    // Q fragments (registers for whole kernel)
    uint32_t qf[4][4];
    {
        const uint32_t qrow = (uint32_t)(w * 16 + (lane & 15));
        const uint32_t qc = (uint32_t)(lane >> 4);
#pragma unroll
        for (int ks = 0; ks < 4; ks++) {
            uint32_t c16 = ks * 2 + qc;
            uint32_t off = qrow * 128 + ((c16 ^ (qrow & 7)) << 4);
            ldm_x4(qf[ks], sb + 8192 + off);
        }
    }

    float m0 = -1e30f, m1 = -1e30f, l0 = 0.f, l1 = 0.f;
    float O[8][4];
#pragma unroll
    for (int g = 0; g < 8; g++)
#pragma unroll
        for (int t = 0; t < 4; t++) O[g][t] = 0.f;

    const uint32_t kr_base = (uint32_t)(((lane & 16) ? 8 : 0) + (lane & 7));
    const uint32_t kc_add  = (uint32_t)((lane & 8) ? 1 : 0);
    const uint32_t vr_base = (uint32_t)(lane & 15);
    const uint32_t vc_add  = (uint32_t)(lane >> 4);

    for (int kt = 0; kt < SEQ / 64; kt++) {
        if (kt > 0) { CP_WAIT1(); __syncthreads(); }
        const uint32_t stg = sb + 24576 + (kt & 1) * 16384;

        // ---- S = Q @ K^T ----
        float S[8][4];
#pragma unroll
        for (int g = 0; g < 8; g++)
#pragma unroll
            for (int t = 0; t < 4; t++) S[g][t] = 0.f;

#pragma unroll
        for (int tg = 0; tg < 4; tg++) {
            const uint32_t row = tg * 16 + kr_base;
#pragma unroll
            for (int ks = 0; ks < 4; ks++) {
                uint32_t c16 = ks * 2 + kc_add;
                uint32_t off = row * 128 + ((c16 ^ (row & 7)) << 4);
                uint32_t fh[4];
                ldm_x4(fh, stg + off);
                mma_f16(S[2 * tg],     qf[ks], &fh[0]);
                mma_f16(S[2 * tg + 1], qf[ks], &fh[2]);
            }
        }

        // ---- mask + online softmax (base 2) ----
        float mt0 = -1e30f, mt1 = -1e30f;
#pragma unroll
        for (int g = 0; g < 8; g++) {
            float2 ma = *(float2*)&madd[kt * 64 + g * 8 + (lane & 3) * 2];
            S[g][0] += ma.x; S[g][1] += ma.y;
            S[g][2] += ma.x; S[g][3] += ma.y;
            mt0 = fmaxf(mt0, fmaxf(S[g][0], S[g][1]));
            mt1 = fmaxf(mt1, fmaxf(S[g][2], S[g][3]));
        }
        mt0 = fmaxf(mt0, __shfl_xor_sync(0xffffffffu, mt0, 1));
        mt0 = fmaxf(mt0, __shfl_xor_sync(0xffffffffu, mt0, 2));
        mt1 = fmaxf(mt1, __shfl_xor_sync(0xffffffffu, mt1, 1));
        mt1 = fmaxf(mt1, __shfl_xor_sync(0xffffffffu, mt1, 2));

        const float mn0 = fmaxf(m0, mt0), mn1 = fmaxf(m1, mt1);
        const float a0 = exp2p(m0 - mn0), a1 = exp2p(m1 - mn1);
        m0 = mn0; m1 = mn1;

        float s0 = 0.f, s1 = 0.f;
        uint32_t ph[4][4];
#pragma unroll
        for (int g = 0; g < 8; g++) {
            float p0 = exp2p(S[g][0] - m0);
            float p1 = exp2p(S[g][1] - m0);
            float p2 = exp2p(S[g][2] - m1);
            float p3 = exp2p(S[g][3] - m1);
            s0 += p0 + p1; s1 += p2 + p3;
            ph[g >> 1][(g & 1) * 2 + 0] = pack_f16x2(p0, p1);
            ph[g >> 1][(g & 1) * 2 + 1] = pack_f16x2(p2, p3);
        }
        s0 += __shfl_xor_sync(0xffffffffu, s0, 1);
        s0 += __shfl_xor_sync(0xffffffffu, s0, 2);
        s1 += __shfl_xor_sync(0xffffffffu, s1, 1);
        s1 += __shfl_xor_sync(0xffffffffu, s1, 2);
        l0 = l0 * a0 + s0;
        l1 = l1 * a1 + s1;

#pragma unroll
        for (int g = 0; g < 8; g++) {
            O[g][0] *= a0; O[g][1] *= a0;
            O[g][2] *= a1; O[g][3] *= a1;
        }

        // ---- O += P @ V ----
#pragma unroll
        for (int gp = 0; gp < 4; gp++) {
#pragma unroll
            for (int j2 = 0; j2 < 4; j2++) {
                uint32_t row = j2 * 16 + vr_base;
                uint32_t c16 = gp * 2 + vc_add;
                uint32_t off = row * 128 + ((c16 ^ (row & 7)) << 4);
                uint32_t fh[4];
                ldm_x4_t(fh, stg + 8192 + off);
                mma_f16(O[2 * gp],     ph[j2], &fh[0]);
                mma_f16(O[2 * gp + 1], ph[j2], &fh[2]);
            }
        }

        __syncthreads();
        if (kt + 2 < SEQ / 64) load_kv(kt & 1, kt + 2);
        CP_COMMIT();
    }

    // ---- epilogue: normalize + fp16 store ----
    const float inv0 = 1.f / l0, inv1 = 1.f / l1;
    const int rg = q0 + w * 16 + (lane >> 2);
    const size_t ob = ((size_t)(b * SEQ)) * D_MODEL + h * DK;
#pragma unroll
    for (int g = 0; g < 8; g++) {
        const int col = g * 8 + (lane & 3) * 2;
        *(uint32_t*)(ctx + ob + (size_t)rg * D_MODEL + col) =
            pack_f16x2(O[g][0] * inv0, O[g][1] * inv0);
        *(uint32_t*)(ctx + ob + (size_t)(rg + 8) * D_MODEL + col) =
            pack_f16x2(O[g][2] * inv1, O[g][3] * inv1);
    }
}

// ---------------- residual add + LayerNorm (optional fp16 copy) ------------
template <bool H16>
__launch_bounds__(128)
__global__ void add_ln_kernel(const float* __restrict__ a,
                              const float* __restrict__ r,
                              const float* __restrict__ g,
                              const float* __restrict__ beta,
                              float* __restrict__ out,
                              __half* __restrict__ oh)
{
    const int row = blockIdx.x;
    const int tid = threadIdx.x;
    const size_t off = (size_t)row * D_MODEL;
    float v[4];
    float s = 0.f, ss = 0.f;
#pragma unroll
    for (int i = 0; i < 4; i++) {
        int c = tid + i * 128;
        float x = a[off + c] + r[off + c];
        v[i] = x; s += x; ss += x * x;
    }
#pragma unroll
    for (int o = 16; o > 0; o >>= 1) {
        s  += __shfl_xor_sync(0xffffffffu, s, o);
        ss += __shfl_xor_sync(0xffffffffu, ss, o);
    }
    __shared__ float rs[4], rss[4];
    int w = tid >> 5, lane = tid & 31;
    if (lane == 0) { rs[w] = s; rss[w] = ss; }
    __syncthreads();
    s  = rs[0]  + rs[1]  + rs[2]  + rs[3];
    ss = rss[0] + rss[1] + rss[2] + rss[3];
    float mu   = s * (1.f / D_MODEL);
    float var  = ss * (1.f / D_MODEL) - mu * mu;
    float rstd = rsqrtf(var + 1e-5f);
#pragma unroll
    for (int i = 0; i < 4; i++) {
        int c = tid + i * 128;
        float y = (v[i] - mu) * rstd * g[c] + beta[c];
        out[off + c] = y;
        if (H16) oh[off + c] = __float2half(y);
    }
}

// ---------------- launch ---------------------------------------------------
extern "C" void kernel_launch(void* const* d_in, const int* in_sizes, int n_in,
                              void* d_out, int out_size)
{
    (void)in_sizes; (void)n_in; (void)out_size;
    const float* x    = (const float*)d_in[0];
    const int*   mask = (const int*)  d_in[1];
    const float* Wq = (const float*)d_in[2];
    const float* bq = (const float*)d_in[3];
    const float* Wk = (const float*)d_in[4];
    const float* bk = (const float*)d_in[5];
    const float* Wv = (const float*)d_in[6];
    const float* bv = (const float*)d_in[7];
    const float* Wo = (const float*)d_in[8];
    const float* bo = (const float*)d_in[9];
    const float* W1 = (const float*)d_in[10];
    const float* b1 = (const float*)d_in[11];
    const float* W2 = (const float*)d_in[12];
    const float* b2 = (const float*)d_in[13];
    const float* g1 = (const float*)d_in[14];
    const float* be1= (const float*)d_in[15];
    const float* g2 = (const float*)d_in[16];
    const float* be2= (const float*)d_in[17];
    float* out = (float*)d_out;

    float *x1, *tmp;
    __half *wt, *xh, *qh, *kh, *vh, *ctx, *x1h, *ffh;
    cudaGetSymbolAddress((void**)&x1,  g_x1);
    cudaGetSymbolAddress((void**)&tmp, g_tmp);
    cudaGetSymbolAddress((void**)&wt,  g_wt);
    cudaGetSymbolAddress((void**)&xh,  g_xh);
    cudaGetSymbolAddress((void**)&qh,  g_qh);
    cudaGetSymbolAddress((void**)&kh,  g_kh);
    cudaGetSymbolAddress((void**)&vh,  g_vh);
    cudaGetSymbolAddress((void**)&ctx, g_ctx);
    cudaGetSymbolAddress((void**)&x1h, g_x1h);
    cudaGetSymbolAddress((void**)&ffh, g_ffh);

    cudaFuncSetAttribute(sgemm_mma_kernel<0>,
                         cudaFuncAttributeMaxDynamicSharedMemorySize, GEMM_SMEM);
    cudaFuncSetAttribute(sgemm_mma_kernel<1>,
                         cudaFuncAttributeMaxDynamicSharedMemorySize, GEMM_SMEM);
    cudaFuncSetAttribute(sgemm_mma_kernel<2>,
                         cudaFuncAttributeMaxDynamicSharedMemorySize, GEMM_SMEM);
    cudaFuncSetAttribute(attn_mma_kernel,
                         cudaFuncAttributeMaxDynamicSharedMemorySize, ATT_SMEM);

    const int M = NTOK;

    // weight transposes + input convert
    transpose4_kernel<<<dim3(16, 16, 4), 256>>>(Wq, Wk, Wv, Wo, wt);
    transpose_kernel<<<dim3(64, 16), 256>>>(W1, wt + OFF_W1, 512, 2048);
    transpose_kernel<<<dim3(16, 64), 256>>>(W2, wt + OFF_W2, 2048, 512);
    cvt_kernel<<<NTOK * D_MODEL / 1024, 256>>>(x, xh);

    // fused QKV projection (fp16 out, Q pre-scaled)
    {
        dim3 grid(1536 / 128, M / 128);
        sgemm_mma_kernel<2><<<grid, 256, GEMM_SMEM>>>(
            xh, wt + OFF_WQKV, bq, bk, bv,
            nullptr, nullptr, qh, kh, vh, M, 1536, 512);
    }

    // flash attention (fp16 tensor cores)
    {
        dim3 grid(SEQ / 128, N_HEADS, BATCH);
        attn_mma_kernel<<<grid, 256, ATT_SMEM>>>(qh, kh, vh, mask, ctx);
    }

    // Wo projection; x1 = LN(x + attn_out)
    {
        dim3 grid(512 / 128, M / 128);
        sgemm_mma_kernel<0><<<grid, 256, GEMM_SMEM>>>(
            ctx, wt + OFF_WO, bo, nullptr, nullptr,
            tmp, nullptr, nullptr, nullptr, nullptr, M, 512, 512);
        add_ln_kernel<true><<<M, 128>>>(x, tmp, g1, be1, x1, x1h);
    }

    // FF
    {
        dim3 grid1(2048 / 128, M / 128);
        sgemm_mma_kernel<1><<<grid1, 256, GEMM_SMEM>>>(
            x1h, wt + OFF_W1, b1, nullptr, nullptr,
            nullptr, ffh, nullptr, nullptr, nullptr, M, 2048, 512);
        dim3 grid2(512 / 128, M / 128);
        sgemm_mma_kernel<0><<<grid2, 256, GEMM_SMEM>>>(
            ffh, wt + OFF_W2, b2, nullptr, nullptr,
            tmp, nullptr, nullptr, nullptr, nullptr, M, 512, 2048);
        add_ln_kernel<false><<<M, 128>>>(x1, tmp, g2, be2, out, nullptr);
    }
}

// round 7
// speedup vs baseline: 6.3814x; 1.0341x over previous
#include <cuda_runtime.h>
#include <cuda_fp16.h>
#include <cstdint>
#include <math.h>

#define D_MODEL 512
#define N_HEADS 8
#define DK      64
#define D_FF    2048
#define BATCH   2
#define SEQ     2048
#define NTOK    (BATCH * SEQ)   // 4096

#define SCALE_Q 0.18033688011112042f   // 0.125 * log2(e)

// ---------------- scratch (device globals; no allocation allowed) ----------
static __device__ float g_x1 [(size_t)NTOK * D_MODEL];
static __device__ float g_tmp[(size_t)NTOK * D_MODEL];

static __device__ __half g_xh [(size_t)NTOK * D_MODEL];
static __device__ __half g_qh [(size_t)NTOK * D_MODEL];
static __device__ __half g_kh [(size_t)NTOK * D_MODEL];
static __device__ __half g_vh [(size_t)NTOK * D_MODEL];
static __device__ __half g_ctx[(size_t)NTOK * D_MODEL];
static __device__ __half g_x1h[(size_t)NTOK * D_MODEL];
static __device__ __half g_ffh[(size_t)NTOK * D_FF];

// transposed fp16 weights: Wt[n][k]; WQ/WK/WV contiguous -> fused [1536,512]
#define OFF_WQKV 0
#define OFF_WO   (3*512*512)
#define OFF_W1   (4*512*512)
#define OFF_W2   (4*512*512 + 2048*512)
#define WT_TOTAL (4*512*512 + 2*2048*512)
static __device__ __half g_wt[WT_TOTAL];

// ======================= PTX helpers (base sm_80+ features) ================
__device__ __forceinline__ uint32_t smem_u32(const void* p) {
    uint32_t a;
    asm("{ .reg .u64 t; cvta.to.shared.u64 t, %1; cvt.u32.u64 %0, t; }"
        : "=r"(a) : "l"(p));
    return a;
}
__device__ __forceinline__ void cp_async16(uint32_t dst, const void* src) {
    asm volatile("cp.async.cg.shared.global [%0], [%1], 16;" :: "r"(dst), "l"(src));
}
#define CP_COMMIT() asm volatile("cp.async.commit_group;" ::: "memory")
#define CP_WAIT1()  asm volatile("cp.async.wait_group 1;" ::: "memory")

__device__ __forceinline__ void ldm_x4(uint32_t* r, uint32_t addr) {
    asm volatile("ldmatrix.sync.aligned.m8n8.x4.shared.b16 {%0,%1,%2,%3}, [%4];"
        : "=r"(r[0]), "=r"(r[1]), "=r"(r[2]), "=r"(r[3]) : "r"(addr));
}
__device__ __forceinline__ void ldm_x4_t(uint32_t* r, uint32_t addr) {
    asm volatile("ldmatrix.sync.aligned.m8n8.x4.trans.shared.b16 {%0,%1,%2,%3}, [%4];"
        : "=r"(r[0]), "=r"(r[1]), "=r"(r[2]), "=r"(r[3]) : "r"(addr));
}
__device__ __forceinline__ void mma_f16(float* c, const uint32_t* a, const uint32_t* b) {
    asm volatile("mma.sync.aligned.m16n8k16.row.col.f32.f16.f16.f32 "
        "{%0,%1,%2,%3}, {%4,%5,%6,%7}, {%8,%9}, {%0,%1,%2,%3};"
        : "+f"(c[0]), "+f"(c[1]), "+f"(c[2]), "+f"(c[3])
        : "r"(a[0]), "r"(a[1]), "r"(a[2]), "r"(a[3]), "r"(b[0]), "r"(b[1]));
}
// pack (lo, hi) -> f16x2 (lo in low half)
__device__ __forceinline__ uint32_t pack_f16x2(float lo, float hi) {
    uint32_t r;
    asm("cvt.rn.f16x2.f32 %0, %1, %2;" : "=r"(r) : "f"(hi), "f"(lo));
    return r;
}

// fast exp2 for x <= 0 on the FMA pipe (no MUFU). abs err ~2e-6.
__device__ __forceinline__ float exp2p(float x) {
    x = fmaxf(x, -126.f);
    float t = __fadd_rn(x, 12582912.f);          // round to nearest int
    float n = __fadd_rn(t, -12582912.f);
    float f = x - n;                              // f in [-0.5, 0.5]
    float p = 1.3333558146e-3f;
    p = fmaf(p, f, 9.6181291077e-3f);
    p = fmaf(p, f, 5.5504108665e-2f);
    p = fmaf(p, f, 2.4022650696e-1f);
    p = fmaf(p, f, 6.9314718056e-1f);
    p = fmaf(p, f, 1.0f);
    int e = __float_as_int(t) - 0x4B400000;       // = (int)n
    return p * __int_as_float((e + 127) << 23);
}

// ============ fused prep: 6 weight transposes + x fp32->fp16 ================
// blocks 0..1023    : Wq/Wk/Wv/Wo (each 256 tiles of 32x32), K=N=512
// blocks 1024..2047 : W1 (K=512 rows, N=2048 cols), 64x16 tiles
// blocks 2048..3071 : W2 (K=2048 rows, N=512 cols), 16x64 tiles
// blocks 3072..5119 : x convert (4096x512 fp32 -> fp16), 1024 elems/block
__device__ __forceinline__ void transpose_tile32(const float* __restrict__ W,
                                                 __half* __restrict__ T,
                                                 int K, int N, int k0, int n0,
                                                 float* tile /* 32*33 */)
{
    const int tx = threadIdx.x & 31, ty = threadIdx.x >> 5;
    for (int i = ty; i < 32; i += 8)
        tile[i * 33 + tx] = W[(size_t)(k0 + i) * N + n0 + tx];
    __syncthreads();
    for (int i = ty; i < 32; i += 8)
        T[(size_t)(n0 + i) * K + k0 + tx] = __float2half(tile[tx * 33 + i]);
}

__global__ void prep_kernel(const float* __restrict__ Wq,
                            const float* __restrict__ Wk,
                            const float* __restrict__ Wv,
                            const float* __restrict__ Wo,
                            const float* __restrict__ W1,
                            const float* __restrict__ W2,
                            const float* __restrict__ x,
                            __half* __restrict__ wt,
                            __half* __restrict__ xh)
{
    __shared__ float tile[32 * 33];
    const int bid = blockIdx.x;
    if (bid < 1024) {
        const int z = bid >> 8, t = bid & 255;
        const float* W = (z == 0) ? Wq : (z == 1) ? Wk : (z == 2) ? Wv : Wo;
        transpose_tile32(W, wt + (size_t)z * 512 * 512, 512, 512,
                         (t >> 4) * 32, (t & 15) * 32, tile);
    } else if (bid < 2048) {
        const int t = bid - 1024;                 // 64 n-tiles x 16 k-tiles
        transpose_tile32(W1, wt + OFF_W1, 512, 2048,
                         (t >> 6) * 32, (t & 63) * 32, tile);
    } else if (bid < 3072) {
        const int t = bid - 2048;                 // 16 n-tiles x 64 k-tiles
        transpose_tile32(W2, wt + OFF_W2, 2048, 512,
                         (t >> 4) * 32, (t & 15) * 32, tile);
    } else {
        const int i = (bid - 3072) * 1024 + threadIdx.x * 4;
        float4 v = *(const float4*)(x + i);
        *(uint2*)(xh + i) = make_uint2(pack_f16x2(v.x, v.y), pack_f16x2(v.z, v.w));
    }
}

// ================ fp16 tensor-core GEMM: C = A @ B^T + bias =================
// A fp16 [M,K] row-major; B fp16 [N,K] K-major. fp32 accumulate.
// Tile 128x128, BK=32, 8 warps (64x32 warp tile), 3-stage cp.async.
// MODE 0: fp32 out (+bias +residual).  MODE 1: fp16 out (+bias, +relu).
// MODE 2: fused QKV (N=1536): fp16 out into q/k/v, per-section bias+scale.
#define ROWB 80
#define TILEB (128 * ROWB)        // 10240
#define GSTAGE (2 * TILEB)        // 20480
#define GEMM_SMEM (3 * GSTAGE)    // 61440

template <int MODE>
__launch_bounds__(256, 2)
__global__ void sgemm_mma_kernel(const __half* __restrict__ A,
                                 const __half* __restrict__ B,
                                 const float* __restrict__ bias0,
                                 const float* __restrict__ bias1,
                                 const float* __restrict__ bias2,
                                 const float* __restrict__ Res,
                                 float* __restrict__ C,
                                 __half* __restrict__ Ch,
                                 __half* __restrict__ Qd,
                                 __half* __restrict__ Kd,
                                 __half* __restrict__ Vd,
                                 int M, int N, int K)
{
    extern __shared__ char smem[];
    const uint32_t sb = smem_u32(smem);
    const int tid = threadIdx.x;
    const int lane = tid & 31, wid = tid >> 5;
    const int wm = wid & 1, wn = wid >> 1;
    const int bm = blockIdx.y * 128;
    const int bn = blockIdx.x * 128;

    const uint32_t offA = (uint32_t)(wm * 64 + (lane & 15)) * ROWB + (lane >> 4) * 16;
    const uint32_t offB = (uint32_t)(wn * 32 + ((lane & 16) ? 8 : 0) + (lane & 7)) * ROWB
                        + ((lane & 8) ? 16 : 0);

    const __half* srcBase[2] = { A + (size_t)bm * K, B + (size_t)bn * K };

    const int nchunks = K >> 5;

    auto load_stage = [&](int s, int c) {
        const int k0 = c << 5;
        const uint32_t stg = sb + s * GSTAGE;
#pragma unroll
        for (int i = 0; i < 4; i++) {
            int idx = i * 256 + tid;
            int tile = idx >> 9;
            int rem = idx & 511;
            int r = rem >> 2;
            int ch = rem & 3;
            uint32_t dst = stg + tile * TILEB + (uint32_t)r * ROWB + ch * 16;
            cp_async16(dst, srcBase[tile] + (size_t)r * K + k0 + ch * 8);
        }
    };

    float acc[4][4][4];
#pragma unroll
    for (int i = 0; i < 4; i++)
#pragma unroll
        for (int j = 0; j < 4; j++)
#pragma unroll
            for (int t = 0; t < 4; t++) acc[i][j][t] = 0.f;

    load_stage(0, 0); CP_COMMIT();
    load_stage(1, 1); CP_COMMIT();

    int s = 0;
    for (int c = 0; c < nchunks; c++) {
        CP_WAIT1();
        __syncthreads();

        int sw = s + 2; if (sw >= 3) sw -= 3;
        if (c + 2 < nchunks) load_stage(sw, c + 2);
        CP_COMMIT();

        const uint32_t base = sb + s * GSTAGE;
        const uint32_t aP = base + offA;
        const uint32_t bP = base + TILEB + offB;

#pragma unroll
        for (int kst = 0; kst < 2; kst++) {
            const uint32_t kb = kst * 32;
            uint32_t fa[4][4], fb[2][4];
#pragma unroll
            for (int i = 0; i < 4; i++)
                ldm_x4(fa[i], aP + i * (16 * ROWB) + kb);
#pragma unroll
            for (int jj = 0; jj < 2; jj++)
                ldm_x4(fb[jj], bP + jj * (16 * ROWB) + kb);
#pragma unroll
            for (int i = 0; i < 4; i++)
#pragma unroll
                for (int j = 0; j < 4; j++)
                    mma_f16(acc[i][j], fa[i], &fb[j >> 1][(j & 1) * 2]);
        }
        if (++s == 3) s = 0;
    }

    // -------- epilogue --------
    const int tr = lane >> 2;
    const int tc2 = (lane & 3) * 2;

    const float* biasS = bias0;
    __half* dstS = Qd;
    float scaleS = 1.f;
    if (MODE == 2) {
        const int sec = bn >> 9;
        biasS  = (sec == 0) ? bias0 : (sec == 1) ? bias1 : bias2;
        dstS   = (sec == 0) ? Qd : (sec == 1) ? Kd : Vd;
        scaleS = (sec == 0) ? SCALE_Q : 1.f;
    }

#pragma unroll
    for (int i = 0; i < 4; i++) {
#pragma unroll
        for (int j = 0; j < 4; j++) {
            const int r = bm + wm * 64 + i * 16 + tr;
            const int ncol = bn + wn * 32 + j * 8 + tc2;
#pragma unroll
            for (int half = 0; half < 2; half++) {
                float v0 = acc[i][j][half * 2 + 0];
                float v1 = acc[i][j][half * 2 + 1];
                const size_t row = (size_t)(r + half * 8);
                if (MODE == 0) {
                    float2 rv = *(const float2*)(Res + row * N + ncol);
                    v0 += bias0[ncol] + rv.x;
                    v1 += bias0[ncol + 1] + rv.y;
                    *(float2*)(C + row * N + ncol) = make_float2(v0, v1);
                } else if (MODE == 1) {
                    v0 = fmaxf(v0 + bias0[ncol], 0.f);
                    v1 = fmaxf(v1 + bias0[ncol + 1], 0.f);
                    *(uint32_t*)(Ch + row * N + ncol) = pack_f16x2(v0, v1);
                } else {
                    const int col = ncol & 511;
                    v0 = (v0 + biasS[col]) * scaleS;
                    v1 = (v1 + biasS[col + 1]) * scaleS;
                    *(uint32_t*)(dstS + row * 512 + col) = pack_f16x2(v0, v1);
                }
            }
        }
    }
}

// ================== tensor-core flash attention (fp16) ======================
// 128 q-rows per CTA, 8 warps (16 rows each), kv tiles of 64 tokens.
// Q pre-scaled by 0.125*log2e; softmax in base-2 with poly exp2 (FMA pipe).
// smem: madd[2048]f (8KB) | Q 16KB | 2 stages x (k 8KB + v 8KB)
#define ATT_SMEM (8192 + 16384 + 2 * 16384)   // 57344

__launch_bounds__(256, 2)
__global__ void attn_mma_kernel(const __half* __restrict__ qh,
                                const __half* __restrict__ kh,
                                const __half* __restrict__ vh,
                                const int* __restrict__ mask,
                                __half* __restrict__ ctx)
{
    extern __shared__ char smc[];
    const uint32_t sb = smem_u32(smc);
    const int tid = threadIdx.x, lane = tid & 31, w = tid >> 5;
    const int qt = blockIdx.x, h = blockIdx.y, b = blockIdx.z;
    const int q0 = qt * 128;
    const size_t qbase  = ((size_t)(b * SEQ + q0)) * D_MODEL + h * DK;
    const size_t kvbase = ((size_t)(b * SEQ)) * D_MODEL + h * DK;

    float* madd = (float*)smc;
    for (int i = tid; i < SEQ; i += 256)
        madd[i] = (mask[b * SEQ + i] == 0) ? -1e9f : 0.f;

    auto load_kv = [&](int stg_i, int ktile) {
        const uint32_t stg = sb + 24576 + stg_i * 16384;
        const size_t tokbase = kvbase + (size_t)ktile * 64 * D_MODEL;
        const __half* srcs[2] = { kh + tokbase, vh + tokbase };
#pragma unroll
        for (int i = 0; i < 4; i++) {
            int idx = i * 256 + tid;
            int t2 = idx >> 9;
            int rem = idx & 511;
            int r = rem >> 3, c = rem & 7;
            uint32_t off = (uint32_t)r * 128 + (uint32_t)((c ^ (r & 7)) << 4);
            cp_async16(stg + t2 * 8192 + off, srcs[t2] + (size_t)r * D_MODEL + c * 8);
        }
    };

    // prologue: Q + stage0, stage1
#pragma unroll
    for (int i = 0; i < 4; i++) {
        int idx = i * 256 + tid;
        int r = idx >> 3, c = idx & 7;
        uint32_t off = (uint32_t)r * 128 + (uint32_t)((c ^ (r & 7)) << 4);
        cp_async16(sb + 8192 + off, qh + qbase + (size_t)r * D_MODEL + c * 8);
    }
    load_kv(0, 0);
    CP_COMMIT();
    load_kv(1, 1);
    CP_COMMIT();

    CP_WAIT1();
    __syncthreads();

    // Q fragments (registers for whole kernel)
    uint32_t qf[4][4];
    {
        const uint32_t qrow = (uint32_t)(w * 16 + (lane & 15));
        const uint32_t qc = (uint32_t)(lane >> 4);
#pragma unroll
        for (int ks = 0; ks < 4; ks++) {
            uint32_t c16 = ks * 2 + qc;
            uint32_t off = qrow * 128 + ((c16 ^ (qrow & 7)) << 4);
            ldm_x4(qf[ks], sb + 8192 + off);
        }
    }

    float m0 = -1e30f, m1 = -1e30f, l0 = 0.f, l1 = 0.f;
    float O[8][4];
#pragma unroll
    for (int g = 0; g < 8; g++)
#pragma unroll
        for (int t = 0; t < 4; t++) O[g][t] = 0.f;

    const uint32_t kr_base = (uint32_t)(((lane & 16) ? 8 : 0) + (lane & 7));
    const uint32_t kc_add  = (uint32_t)((lane & 8) ? 1 : 0);
    const uint32_t vr_base = (uint32_t)(lane & 15);
    const uint32_t vc_add  = (uint32_t)(lane >> 4);

    for (int kt = 0; kt < SEQ / 64; kt++) {
        if (kt > 0) { CP_WAIT1(); __syncthreads(); }
        const uint32_t stg = sb + 24576 + (kt & 1) * 16384;

        // ---- S = Q @ K^T ----
        float S[8][4];
#pragma unroll
        for (int g = 0; g < 8; g++)
#pragma unroll
            for (int t = 0; t < 4; t++) S[g][t] = 0.f;

#pragma unroll
        for (int tg = 0; tg < 4; tg++) {
            const uint32_t row = tg * 16 + kr_base;
#pragma unroll
            for (int ks = 0; ks < 4; ks++) {
                uint32_t c16 = ks * 2 + kc_add;
                uint32_t off = row * 128 + ((c16 ^ (row & 7)) << 4);
                uint32_t fh[4];
                ldm_x4(fh, stg + off);
                mma_f16(S[2 * tg],     qf[ks], &fh[0]);
                mma_f16(S[2 * tg + 1], qf[ks], &fh[2]);
            }
        }

        // ---- mask + online softmax (base 2) ----
        float mt0 = -1e30f, mt1 = -1e30f;
#pragma unroll
        for (int g = 0; g < 8; g++) {
            float2 ma = *(float2*)&madd[kt * 64 + g * 8 + (lane & 3) * 2];
            S[g][0] += ma.x; S[g][1] += ma.y;
            S[g][2] += ma.x; S[g][3] += ma.y;
            mt0 = fmaxf(mt0, fmaxf(S[g][0], S[g][1]));
            mt1 = fmaxf(mt1, fmaxf(S[g][2], S[g][3]));
        }
        mt0 = fmaxf(mt0, __shfl_xor_sync(0xffffffffu, mt0, 1));
        mt0 = fmaxf(mt0, __shfl_xor_sync(0xffffffffu, mt0, 2));
        mt1 = fmaxf(mt1, __shfl_xor_sync(0xffffffffu, mt1, 1));
        mt1 = fmaxf(mt1, __shfl_xor_sync(0xffffffffu, mt1, 2));

        const float mn0 = fmaxf(m0, mt0), mn1 = fmaxf(m1, mt1);
        const float a0 = exp2p(m0 - mn0), a1 = exp2p(m1 - mn1);
        m0 = mn0; m1 = mn1;

        float s0 = 0.f, s1 = 0.f;
        uint32_t ph[4][4];
#pragma unroll
        for (int g = 0; g < 8; g++) {
            float p0 = exp2p(S[g][0] - m0);
            float p1 = exp2p(S[g][1] - m0);
            float p2 = exp2p(S[g][2] - m1);
            float p3 = exp2p(S[g][3] - m1);
            s0 += p0 + p1; s1 += p2 + p3;
            ph[g >> 1][(g & 1) * 2 + 0] = pack_f16x2(p0, p1);
            ph[g >> 1][(g & 1) * 2 + 1] = pack_f16x2(p2, p3);
        }
        s0 += __shfl_xor_sync(0xffffffffu, s0, 1);
        s0 += __shfl_xor_sync(0xffffffffu, s0, 2);
        s1 += __shfl_xor_sync(0xffffffffu, s1, 1);
        s1 += __shfl_xor_sync(0xffffffffu, s1, 2);
        l0 = l0 * a0 + s0;
        l1 = l1 * a1 + s1;

#pragma unroll
        for (int g = 0; g < 8; g++) {
            O[g][0] *= a0; O[g][1] *= a0;
            O[g][2] *= a1; O[g][3] *= a1;
        }

        // ---- O += P @ V ----
#pragma unroll
        for (int gp = 0; gp < 4; gp++) {
#pragma unroll
            for (int j2 = 0; j2 < 4; j2++) {
                uint32_t row = j2 * 16 + vr_base;
                uint32_t c16 = gp * 2 + vc_add;
                uint32_t off = row * 128 + ((c16 ^ (row & 7)) << 4);
                uint32_t fh[4];
                ldm_x4_t(fh, stg + 8192 + off);
                mma_f16(O[2 * gp],     ph[j2], &fh[0]);
                mma_f16(O[2 * gp + 1], ph[j2], &fh[2]);
            }
        }

        __syncthreads();
        if (kt + 2 < SEQ / 64) load_kv(kt & 1, kt + 2);
        CP_COMMIT();
    }

    // ---- epilogue: normalize + fp16 store ----
    const float inv0 = 1.f / l0, inv1 = 1.f / l1;
    const int rg = q0 + w * 16 + (lane >> 2);
    const size_t ob = ((size_t)(b * SEQ)) * D_MODEL + h * DK;
#pragma unroll
    for (int g = 0; g < 8; g++) {
        const int col = g * 8 + (lane & 3) * 2;
        *(uint32_t*)(ctx + ob + (size_t)rg * D_MODEL + col) =
            pack_f16x2(O[g][0] * inv0, O[g][1] * inv0);
        *(uint32_t*)(ctx + ob + (size_t)(rg + 8) * D_MODEL + col) =
            pack_f16x2(O[g][2] * inv1, O[g][3] * inv1);
    }
}

// -------- LayerNorm over precomputed sum buffer (optional fp16 copy) -------
template <bool H16>
__launch_bounds__(128)
__global__ void ln_kernel(const float* __restrict__ a,
                          const float* __restrict__ g,
                          const float* __restrict__ beta,
                          float* __restrict__ out,
                          __half* __restrict__ oh)
{
    const int row = blockIdx.x;
    const int tid = threadIdx.x;
    const size_t off = (size_t)row * D_MODEL;
    float v[4];
    float s = 0.f, ss = 0.f;
#pragma unroll
    for (int i = 0; i < 4; i++) {
        int c = tid + i * 128;
        float x = a[off + c];
        v[i] = x; s += x; ss += x * x;
    }
#pragma unroll
    for (int o = 16; o > 0; o >>= 1) {
        s  += __shfl_xor_sync(0xffffffffu, s, o);
        ss += __shfl_xor_sync(0xffffffffu, ss, o);
    }
    __shared__ float rs[4], rss[4];
    int w = tid >> 5, lane = tid & 31;
    if (lane == 0) { rs[w] = s; rss[w] = ss; }
    __syncthreads();
    s  = rs[0]  + rs[1]  + rs[2]  + rs[3];
    ss = rss[0] + rss[1] + rss[2] + rss[3];
    float mu   = s * (1.f / D_MODEL);
    float var  = ss * (1.f / D_MODEL) - mu * mu;
    float rstd = rsqrtf(var + 1e-5f);
#pragma unroll
    for (int i = 0; i < 4; i++) {
        int c = tid + i * 128;
        float y = (v[i] - mu) * rstd * g[c] + beta[c];
        out[off + c] = y;
        if (H16) oh[off + c] = __float2half(y);
    }
}

// ---------------- launch ---------------------------------------------------
extern "C" void kernel_launch(void* const* d_in, const int* in_sizes, int n_in,
                              void* d_out, int out_size)
{
    (void)in_sizes; (void)n_in; (void)out_size;
    const float* x    = (const float*)d_in[0];
    const int*   mask = (const int*)  d_in[1];
    const float* Wq = (const float*)d_in[2];
    const float* bq = (const float*)d_in[3];
    const float* Wk = (const float*)d_in[4];
    const float* bk = (const float*)d_in[5];
    const float* Wv = (const float*)d_in[6];
    const float* bv = (const float*)d_in[7];
    const float* Wo = (const float*)d_in[8];
    const float* bo = (const float*)d_in[9];
    const float* W1 = (const float*)d_in[10];
    const float* b1 = (const float*)d_in[11];
    const float* W2 = (const float*)d_in[12];
    const float* b2 = (const float*)d_in[13];
    const float* g1 = (const float*)d_in[14];
    const float* be1= (const float*)d_in[15];
    const float* g2 = (const float*)d_in[16];
    const float* be2= (const float*)d_in[17];
    float* out = (float*)d_out;

    float *x1, *tmp;
    __half *wt, *xh, *qh, *kh, *vh, *ctx, *x1h, *ffh;
    cudaGetSymbolAddress((void**)&x1,  g_x1);
    cudaGetSymbolAddress((void**)&tmp, g_tmp);
    cudaGetSymbolAddress((void**)&wt,  g_wt);
    cudaGetSymbolAddress((void**)&xh,  g_xh);
    cudaGetSymbolAddress((void**)&qh,  g_qh);
    cudaGetSymbolAddress((void**)&kh,  g_kh);
    cudaGetSymbolAddress((void**)&vh,  g_vh);
    cudaGetSymbolAddress((void**)&ctx, g_ctx);
    cudaGetSymbolAddress((void**)&x1h, g_x1h);
    cudaGetSymbolAddress((void**)&ffh, g_ffh);

    cudaFuncSetAttribute(sgemm_mma_kernel<0>,
                         cudaFuncAttributeMaxDynamicSharedMemorySize, GEMM_SMEM);
    cudaFuncSetAttribute(sgemm_mma_kernel<1>,
                         cudaFuncAttributeMaxDynamicSharedMemorySize, GEMM_SMEM);
    cudaFuncSetAttribute(sgemm_mma_kernel<2>,
                         cudaFuncAttributeMaxDynamicSharedMemorySize, GEMM_SMEM);
    cudaFuncSetAttribute(attn_mma_kernel,
                         cudaFuncAttributeMaxDynamicSharedMemorySize, ATT_SMEM);

    const int M = NTOK;

    // fused prep: all weight transposes + x convert (one launch)
    prep_kernel<<<5120, 256>>>(Wq, Wk, Wv, Wo, W1, W2, x, wt, xh);

    // fused QKV projection (fp16 out, Q pre-scaled)
    {
        dim3 grid(1536 / 128, M / 128);
        sgemm_mma_kernel<2><<<grid, 256, GEMM_SMEM>>>(
            xh, wt + OFF_WQKV, bq, bk, bv, nullptr,
            nullptr, nullptr, qh, kh, vh, M, 1536, 512);
    }

    // flash attention (fp16 tensor cores)
    {
        dim3 grid(SEQ / 128, N_HEADS, BATCH);
        attn_mma_kernel<<<grid, 256, ATT_SMEM>>>(qh, kh, vh, mask, ctx);
    }

    // Wo projection (+bias +residual x) -> tmp; x1 = LN(tmp)
    {
        dim3 grid(512 / 128, M / 128);
        sgemm_mma_kernel<0><<<grid, 256, GEMM_SMEM>>>(
            ctx, wt + OFF_WO, bo, nullptr, nullptr, x,
            tmp, nullptr, nullptr, nullptr, nullptr, M, 512, 512);
        ln_kernel<true><<<M, 128>>>(tmp, g1, be1, x1, x1h);
    }

    // FF
    {
        dim3 grid1(2048 / 128, M / 128);
        sgemm_mma_kernel<1><<<grid1, 256, GEMM_SMEM>>>(
            x1h, wt + OFF_W1, b1, nullptr, nullptr, nullptr,
            nullptr, ffh, nullptr, nullptr, nullptr, M, 2048, 512);
        dim3 grid2(512 / 128, M / 128);
        sgemm_mma_kernel<0><<<grid2, 256, GEMM_SMEM>>>(
            ffh, wt + OFF_W2, b2, nullptr, nullptr, x1,
            tmp, nullptr, nullptr, nullptr, nullptr, M, 512, 2048);
        ln_kernel<false><<<M, 128>>>(tmp, g2, be2, out, nullptr);
    }
}

// round 8
// speedup vs baseline: 6.3878x; 1.0010x over previous
#include <cuda_runtime.h>
#include <cuda_fp16.h>
#include <cstdint>
#include <math.h>

#define D_MODEL 512
#define N_HEADS 8
#define DK      64
#define D_FF    2048
#define BATCH   2
#define SEQ     2048
#define NTOK    (BATCH * SEQ)   // 4096

#define SCALE_Q 0.18033688011112042f   // 0.125 * log2(e)

// ---------------- scratch (device globals; no allocation allowed) ----------
static __device__ float g_x1 [(size_t)NTOK * D_MODEL];
static __device__ float g_tmp[(size_t)NTOK * D_MODEL];

static __device__ __half g_xh [(size_t)NTOK * D_MODEL];
static __device__ __half g_qh [(size_t)NTOK * D_MODEL];
static __device__ __half g_kh [(size_t)NTOK * D_MODEL];
static __device__ __half g_vh [(size_t)NTOK * D_MODEL];
static __device__ __half g_ctx[(size_t)NTOK * D_MODEL];
static __device__ __half g_x1h[(size_t)NTOK * D_MODEL];
static __device__ __half g_ffh[(size_t)NTOK * D_FF];

// transposed fp16 weights: Wt[n][k]; WQ/WK/WV contiguous -> fused [1536,512]
#define OFF_WQKV 0
#define OFF_WO   (3*512*512)
#define OFF_W1   (4*512*512)
#define OFF_W2   (4*512*512 + 2048*512)
#define WT_TOTAL (4*512*512 + 2*2048*512)
static __device__ __half g_wt[WT_TOTAL];

// ======================= PTX helpers (base sm_80+ features) ================
__device__ __forceinline__ uint32_t smem_u32(const void* p) {
    uint32_t a;
    asm("{ .reg .u64 t; cvta.to.shared.u64 t, %1; cvt.u32.u64 %0, t; }"
        : "=r"(a) : "l"(p));
    return a;
}
__device__ __forceinline__ void cp_async16(uint32_t dst, const void* src) {
    asm volatile("cp.async.cg.shared.global [%0], [%1], 16;" :: "r"(dst), "l"(src));
}
#define CP_COMMIT() asm volatile("cp.async.commit_group;" ::: "memory")
#define CP_WAIT2()  asm volatile("cp.async.wait_group 2;" ::: "memory")

__device__ __forceinline__ void ldm_x4(uint32_t* r, uint32_t addr) {
    asm volatile("ldmatrix.sync.aligned.m8n8.x4.shared.b16 {%0,%1,%2,%3}, [%4];"
        : "=r"(r[0]), "=r"(r[1]), "=r"(r[2]), "=r"(r[3]) : "r"(addr));
}
__device__ __forceinline__ void ldm_x4_t(uint32_t* r, uint32_t addr) {
    asm volatile("ldmatrix.sync.aligned.m8n8.x4.trans.shared.b16 {%0,%1,%2,%3}, [%4];"
        : "=r"(r[0]), "=r"(r[1]), "=r"(r[2]), "=r"(r[3]) : "r"(addr));
}
__device__ __forceinline__ void mma_f16(float* c, const uint32_t* a, const uint32_t* b) {
    asm volatile("mma.sync.aligned.m16n8k16.row.col.f32.f16.f16.f32 "
        "{%0,%1,%2,%3}, {%4,%5,%6,%7}, {%8,%9}, {%0,%1,%2,%3};"
        : "+f"(c[0]), "+f"(c[1]), "+f"(c[2]), "+f"(c[3])
        : "r"(a[0]), "r"(a[1]), "r"(a[2]), "r"(a[3]), "r"(b[0]), "r"(b[1]));
}
// pack (lo, hi) -> f16x2 (lo in low half)
__device__ __forceinline__ uint32_t pack_f16x2(float lo, float hi) {
    uint32_t r;
    asm("cvt.rn.f16x2.f32 %0, %1, %2;" : "=r"(r) : "f"(hi), "f"(lo));
    return r;
}

// fast exp2 for x <= 0 on the FMA pipe (no MUFU). abs err ~2e-6.
__device__ __forceinline__ float exp2p(float x) {
    x = fmaxf(x, -126.f);
    float t = __fadd_rn(x, 12582912.f);          // round to nearest int
    float n = __fadd_rn(t, -12582912.f);
    float f = x - n;                              // f in [-0.5, 0.5]
    float p = 1.3333558146e-3f;
    p = fmaf(p, f, 9.6181291077e-3f);
    p = fmaf(p, f, 5.5504108665e-2f);
    p = fmaf(p, f, 2.4022650696e-1f);
    p = fmaf(p, f, 6.9314718056e-1f);
    p = fmaf(p, f, 1.0f);
    int e = __float_as_int(t) - 0x4B400000;       // = (int)n
    return p * __int_as_float((e + 127) << 23);
}

// ============ fused prep: 6 weight transposes + x fp32->fp16 ================
__device__ __forceinline__ void transpose_tile32(const float* __restrict__ W,
                                                 __half* __restrict__ T,
                                                 int K, int N, int k0, int n0,
                                                 float* tile /* 32*33 */)
{
    const int tx = threadIdx.x & 31, ty = threadIdx.x >> 5;
    for (int i = ty; i < 32; i += 8)
        tile[i * 33 + tx] = W[(size_t)(k0 + i) * N + n0 + tx];
    __syncthreads();
    for (int i = ty; i < 32; i += 8)
        T[(size_t)(n0 + i) * K + k0 + tx] = __float2half(tile[tx * 33 + i]);
}

__global__ void prep_kernel(const float* __restrict__ Wq,
                            const float* __restrict__ Wk,
                            const float* __restrict__ Wv,
                            const float* __restrict__ Wo,
                            const float* __restrict__ W1,
                            const float* __restrict__ W2,
                            const float* __restrict__ x,
                            __half* __restrict__ wt,
                            __half* __restrict__ xh)
{
    __shared__ float tile[32 * 33];
    const int bid = blockIdx.x;
    if (bid < 1024) {
        const int z = bid >> 8, t = bid & 255;
        const float* W = (z == 0) ? Wq : (z == 1) ? Wk : (z == 2) ? Wv : Wo;
        transpose_tile32(W, wt + (size_t)z * 512 * 512, 512, 512,
                         (t >> 4) * 32, (t & 15) * 32, tile);
    } else if (bid < 2048) {
        const int t = bid - 1024;
        transpose_tile32(W1, wt + OFF_W1, 512, 2048,
                         (t >> 6) * 32, (t & 63) * 32, tile);
    } else if (bid < 3072) {
        const int t = bid - 2048;
        transpose_tile32(W2, wt + OFF_W2, 2048, 512,
                         (t >> 4) * 32, (t & 15) * 32, tile);
    } else {
        const int i = (bid - 3072) * 1024 + threadIdx.x * 4;
        float4 v = *(const float4*)(x + i);
        *(uint2*)(xh + i) = make_uint2(pack_f16x2(v.x, v.y), pack_f16x2(v.z, v.w));
    }
}

// ================ fp16 tensor-core GEMM: C = A @ B^T + bias =================
// A fp16 [M,K] row-major; B fp16 [N,K] K-major. fp32 accumulate.
// Tile 128x128, BK=32, 8 warps (64x32 warp tile), 4-stage cp.async pipeline
// (3 chunk-loads in flight -> ~3x T_iter latency coverage).
// MODE 0: fp32 out (+bias +residual).  MODE 1: fp16 out (+bias, +relu).
// MODE 2: fused QKV (N=1536): fp16 out into q/k/v, per-section bias+scale.
#define ROWB 80
#define TILEB (128 * ROWB)        // 10240
#define GSTAGE (2 * TILEB)        // 20480
#define GEMM_SMEM (4 * GSTAGE)    // 81920

template <int MODE>
__launch_bounds__(256, 2)
__global__ void sgemm_mma_kernel(const __half* __restrict__ A,
                                 const __half* __restrict__ B,
                                 const float* __restrict__ bias0,
                                 const float* __restrict__ bias1,
                                 const float* __restrict__ bias2,
                                 const float* __restrict__ Res,
                                 float* __restrict__ C,
                                 __half* __restrict__ Ch,
                                 __half* __restrict__ Qd,
                                 __half* __restrict__ Kd,
                                 __half* __restrict__ Vd,
                                 int M, int N, int K)
{
    extern __shared__ char smem[];
    const uint32_t sb = smem_u32(smem);
    const int tid = threadIdx.x;
    const int lane = tid & 31, wid = tid >> 5;
    const int wm = wid & 1, wn = wid >> 1;
    const int bm = blockIdx.y * 128;
    const int bn = blockIdx.x * 128;

    const uint32_t offA = (uint32_t)(wm * 64 + (lane & 15)) * ROWB + (lane >> 4) * 16;
    const uint32_t offB = (uint32_t)(wn * 32 + ((lane & 16) ? 8 : 0) + (lane & 7)) * ROWB
                        + ((lane & 8) ? 16 : 0);

    const __half* srcBase[2] = { A + (size_t)bm * K, B + (size_t)bn * K };

    const int nchunks = K >> 5;

    auto load_stage = [&](int s, int c) {
        const int k0 = c << 5;
        const uint32_t stg = sb + s * GSTAGE;
#pragma unroll
        for (int i = 0; i < 4; i++) {
            int idx = i * 256 + tid;
            int tile = idx >> 9;
            int rem = idx & 511;
            int r = rem >> 2;
            int ch = rem & 3;
            uint32_t dst = stg + tile * TILEB + (uint32_t)r * ROWB + ch * 16;
            cp_async16(dst, srcBase[tile] + (size_t)r * K + k0 + ch * 8);
        }
    };

    float acc[4][4][4];
#pragma unroll
    for (int i = 0; i < 4; i++)
#pragma unroll
        for (int j = 0; j < 4; j++)
#pragma unroll
            for (int t = 0; t < 4; t++) acc[i][j][t] = 0.f;

    load_stage(0, 0); CP_COMMIT();
    load_stage(1, 1); CP_COMMIT();
    load_stage(2, 2); CP_COMMIT();

    int s = 0;
    for (int c = 0; c < nchunks; c++) {
        CP_WAIT2();
        __syncthreads();

        int sw = s + 3; if (sw >= 4) sw -= 4;
        if (c + 3 < nchunks) load_stage(sw, c + 3);
        CP_COMMIT();

        const uint32_t base = sb + s * GSTAGE;
        const uint32_t aP = base + offA;
        const uint32_t bP = base + TILEB + offB;

#pragma unroll
        for (int kst = 0; kst < 2; kst++) {
            const uint32_t kb = kst * 32;
            uint32_t fa[4][4], fb[2][4];
#pragma unroll
            for (int i = 0; i < 4; i++)
                ldm_x4(fa[i], aP + i * (16 * ROWB) + kb);
#pragma unroll
            for (int jj = 0; jj < 2; jj++)
                ldm_x4(fb[jj], bP + jj * (16 * ROWB) + kb);
#pragma unroll
            for (int i = 0; i < 4; i++)
#pragma unroll
                for (int j = 0; j < 4; j++)
                    mma_f16(acc[i][j], fa[i], &fb[j >> 1][(j & 1) * 2]);
        }
        if (++s == 4) s = 0;
    }

    // -------- epilogue --------
    const int tr = lane >> 2;
    const int tc2 = (lane & 3) * 2;

    const float* biasS = bias0;
    __half* dstS = Qd;
    float scaleS = 1.f;
    if (MODE == 2) {
        const int sec = bn >> 9;
        biasS  = (sec == 0) ? bias0 : (sec == 1) ? bias1 : bias2;
        dstS   = (sec == 0) ? Qd : (sec == 1) ? Kd : Vd;
        scaleS = (sec == 0) ? SCALE_Q : 1.f;
    }

#pragma unroll
    for (int i = 0; i < 4; i++) {
#pragma unroll
        for (int j = 0; j < 4; j++) {
            const int r = bm + wm * 64 + i * 16 + tr;
            const int ncol = bn + wn * 32 + j * 8 + tc2;
#pragma unroll
            for (int half = 0; half < 2; half++) {
                float v0 = acc[i][j][half * 2 + 0];
                float v1 = acc[i][j][half * 2 + 1];
                const size_t row = (size_t)(r + half * 8);
                if (MODE == 0) {
                    float2 rv = *(const float2*)(Res + row * N + ncol);
                    v0 += bias0[ncol] + rv.x;
                    v1 += bias0[ncol + 1] + rv.y;
                    *(float2*)(C + row * N + ncol) = make_float2(v0, v1);
                } else if (MODE == 1) {
                    v0 = fmaxf(v0 + bias0[ncol], 0.f);
                    v1 = fmaxf(v1 + bias0[ncol + 1], 0.f);
                    *(uint32_t*)(Ch + row * N + ncol) = pack_f16x2(v0, v1);
                } else {
                    const int col = ncol & 511;
                    v0 = (v0 + biasS[col]) * scaleS;
                    v1 = (v1 + biasS[col + 1]) * scaleS;
                    *(uint32_t*)(dstS + row * 512 + col) = pack_f16x2(v0, v1);
                }
            }
        }
    }
}

// ================== tensor-core flash attention (fp16) ======================
// 128 q-rows per CTA, 8 warps (16 rows each), kv tiles of 64 tokens.
// Q pre-scaled by 0.125*log2e; softmax in base-2 with poly exp2 (FMA pipe).
// smem: madd[2048]f (8KB) | Q 16KB | 3 stages x (k 8KB + v 8KB)
#define ATT_KVOFF 24576
#define ATT_SMEM (8192 + 16384 + 3 * 16384)   // 73728

__launch_bounds__(256, 2)
__global__ void attn_mma_kernel(const __half* __restrict__ qh,
                                const __half* __restrict__ kh,
                                const __half* __restrict__ vh,
                                const int* __restrict__ mask,
                                __half* __restrict__ ctx)
{
    extern __shared__ char smc[];
    const uint32_t sb = smem_u32(smc);
    const int tid = threadIdx.x, lane = tid & 31, w = tid >> 5;
    const int qt = blockIdx.x, h = blockIdx.y, b = blockIdx.z;
    const int q0 = qt * 128;
    const size_t qbase  = ((size_t)(b * SEQ + q0)) * D_MODEL + h * DK;
    const size_t kvbase = ((size_t)(b * SEQ)) * D_MODEL + h * DK;

    float* madd = (float*)smc;
    for (int i = tid; i < SEQ; i += 256)
        madd[i] = (mask[b * SEQ + i] == 0) ? -1e9f : 0.f;

    auto load_kv = [&](int stg_i, int ktile) {
        const uint32_t stg = sb + ATT_KVOFF + stg_i * 16384;
        const size_t tokbase = kvbase + (size_t)ktile * 64 * D_MODEL;
        const __half* srcs[2] = { kh + tokbase, vh + tokbase };
#pragma unroll
        for (int i = 0; i < 4; i++) {
            int idx = i * 256 + tid;
            int t2 = idx >> 9;
            int rem = idx & 511;
            int r = rem >> 3, c = rem & 7;
            uint32_t off = (uint32_t)r * 128 + (uint32_t)((c ^ (r & 7)) << 4);
            cp_async16(stg + t2 * 8192 + off, srcs[t2] + (size_t)r * D_MODEL + c * 8);
        }
    };

    // prologue: Q + kv0 (group 0), kv1, kv2
#pragma unroll
    for (int i = 0; i < 4; i++) {
        int idx = i * 256 + tid;
        int r = idx >> 3, c = idx & 7;
        uint32_t off = (uint32_t)r * 128 + (uint32_t)((c ^ (r & 7)) << 4);
        cp_async16(sb + 8192 + off, qh + qbase + (size_t)r * D_MODEL + c * 8);
    }
    load_kv(0, 0);
    CP_COMMIT();
    load_kv(1, 1);
    CP_COMMIT();
    load_kv(2, 2);
    CP_COMMIT();

    CP_WAIT2();
    __syncthreads();

    // Q fragments (registers for whole kernel)
    uint32_t qf[4][4];
    {
        const uint32_t qrow = (uint32_t)(w * 16 + (lane & 15));
        const uint32_t qc = (uint32_t)(lane >> 4);
#pragma unroll
        for (int ks = 0; ks < 4; ks++) {
            uint32_t c16 = ks * 2 + qc;
            uint32_t off = qrow * 128 + ((c16 ^ (qrow & 7)) << 4);
            ldm_x4(qf[ks], sb + 8192 + off);
        }
    }

    float m0 = -1e30f, m1 = -1e30f, l0 = 0.f, l1 = 0.f;
    float O[8][4];
#pragma unroll
    for (int g = 0; g < 8; g++)
#pragma unroll
        for (int t = 0; t < 4; t++) O[g][t] = 0.f;

    const uint32_t kr_base = (uint32_t)(((lane & 16) ? 8 : 0) + (lane & 7));
    const uint32_t kc_add  = (uint32_t)((lane & 8) ? 1 : 0);
    const uint32_t vr_base = (uint32_t)(lane & 15);
    const uint32_t vc_add  = (uint32_t)(lane >> 4);

    int stg_i = 0;
    for (int kt = 0; kt < SEQ / 64; kt++) {
        if (kt > 0) { CP_WAIT2(); __syncthreads(); }
        const uint32_t stg = sb + ATT_KVOFF + stg_i * 16384;

        // ---- S = Q @ K^T ----
        float S[8][4];
#pragma unroll
        for (int g = 0; g < 8; g++)
#pragma unroll
            for (int t = 0; t < 4; t++) S[g][t] = 0.f;

#pragma unroll
        for (int tg = 0; tg < 4; tg++) {
            const uint32_t row = tg * 16 + kr_base;
#pragma unroll
            for (int ks = 0; ks < 4; ks++) {
                uint32_t c16 = ks * 2 + kc_add;
                uint32_t off = row * 128 + ((c16 ^ (row & 7)) << 4);
                uint32_t fh[4];
                ldm_x4(fh, stg + off);
                mma_f16(S[2 * tg],     qf[ks], &fh[0]);
                mma_f16(S[2 * tg + 1], qf[ks], &fh[2]);
            }
        }

        // ---- mask + online softmax (base 2) ----
        float mt0 = -1e30f, mt1 = -1e30f;
#pragma unroll
        for (int g = 0; g < 8; g++) {
            float2 ma = *(float2*)&madd[kt * 64 + g * 8 + (lane & 3) * 2];
            S[g][0] += ma.x; S[g][1] += ma.y;
            S[g][2] += ma.x; S[g][3] += ma.y;
            mt0 = fmaxf(mt0, fmaxf(S[g][0], S[g][1]));
            mt1 = fmaxf(mt1, fmaxf(S[g][2], S[g][3]));
        }
        mt0 = fmaxf(mt0, __shfl_xor_sync(0xffffffffu, mt0, 1));
        mt0 = fmaxf(mt0, __shfl_xor_sync(0xffffffffu, mt0, 2));
        mt1 = fmaxf(mt1, __shfl_xor_sync(0xffffffffu, mt1, 1));
        mt1 = fmaxf(mt1, __shfl_xor_sync(0xffffffffu, mt1, 2));

        const float mn0 = fmaxf(m0, mt0), mn1 = fmaxf(m1, mt1);
        const float a0 = exp2p(m0 - mn0), a1 = exp2p(m1 - mn1);
        m0 = mn0; m1 = mn1;

        float s0 = 0.f, s1 = 0.f;
        uint32_t ph[4][4];
#pragma unroll
        for (int g = 0; g < 8; g++) {
            float p0 = exp2p(S[g][0] - m0);
            float p1 = exp2p(S[g][1] - m0);
            float p2 = exp2p(S[g][2] - m1);
            float p3 = exp2p(S[g][3] - m1);
            s0 += p0 + p1; s1 += p2 + p3;
            ph[g >> 1][(g & 1) * 2 + 0] = pack_f16x2(p0, p1);
            ph[g >> 1][(g & 1) * 2 + 1] = pack_f16x2(p2, p3);
        }
        s0 += __shfl_xor_sync(0xffffffffu, s0, 1);
        s0 += __shfl_xor_sync(0xffffffffu, s0, 2);
        s1 += __shfl_xor_sync(0xffffffffu, s1, 1);
        s1 += __shfl_xor_sync(0xffffffffu, s1, 2);
        l0 = l0 * a0 + s0;
        l1 = l1 * a1 + s1;

#pragma unroll
        for (int g = 0; g < 8; g++) {
            O[g][0] *= a0; O[g][1] *= a0;
            O[g][2] *= a1; O[g][3] *= a1;
        }

        // ---- O += P @ V ----
#pragma unroll
        for (int gp = 0; gp < 4; gp++) {
#pragma unroll
            for (int j2 = 0; j2 < 4; j2++) {
                uint32_t row = j2 * 16 + vr_base;
                uint32_t c16 = gp * 2 + vc_add;
                uint32_t off = row * 128 + ((c16 ^ (row & 7)) << 4);
                uint32_t fh[4];
                ldm_x4_t(fh, stg + 8192 + off);
                mma_f16(O[2 * gp],     ph[j2], &fh[0]);
                mma_f16(O[2 * gp + 1], ph[j2], &fh[2]);
            }
        }

        __syncthreads();
        if (kt + 3 < SEQ / 64) load_kv(stg_i, kt + 3);
        CP_COMMIT();
        if (++stg_i == 3) stg_i = 0;
    }

    // ---- epilogue: normalize + fp16 store ----
    const float inv0 = 1.f / l0, inv1 = 1.f / l1;
    const int rg = q0 + w * 16 + (lane >> 2);
    const size_t ob = ((size_t)(b * SEQ)) * D_MODEL + h * DK;
#pragma unroll
    for (int g = 0; g < 8; g++) {
        const int col = g * 8 + (lane & 3) * 2;
        *(uint32_t*)(ctx + ob + (size_t)rg * D_MODEL + col) =
            pack_f16x2(O[g][0] * inv0, O[g][1] * inv0);
        *(uint32_t*)(ctx + ob + (size_t)(rg + 8) * D_MODEL + col) =
            pack_f16x2(O[g][2] * inv1, O[g][3] * inv1);
    }
}

// -------- LayerNorm over precomputed sum buffer (optional fp16 copy) -------
template <bool H16>
__launch_bounds__(128)
__global__ void ln_kernel(const float* __restrict__ a,
                          const float* __restrict__ g,
                          const float* __restrict__ beta,
                          float* __restrict__ out,
                          __half* __restrict__ oh)
{
    const int row = blockIdx.x;
    const int tid = threadIdx.x;
    const size_t off = (size_t)row * D_MODEL;
    float v[4];
    float s = 0.f, ss = 0.f;
#pragma unroll
    for (int i = 0; i < 4; i++) {
        int c = tid + i * 128;
        float x = a[off + c];
        v[i] = x; s += x; ss += x * x;
    }
#pragma unroll
    for (int o = 16; o > 0; o >>= 1) {
        s  += __shfl_xor_sync(0xffffffffu, s, o);
        ss += __shfl_xor_sync(0xffffffffu, ss, o);
    }
    __shared__ float rs[4], rss[4];
    int w = tid >> 5, lane = tid & 31;
    if (lane == 0) { rs[w] = s; rss[w] = ss; }
    __syncthreads();
    s  = rs[0]  + rs[1]  + rs[2]  + rs[3];
    ss = rss[0] + rss[1] + rss[2] + rss[3];
    float mu   = s * (1.f / D_MODEL);
    float var  = ss * (1.f / D_MODEL) - mu * mu;
    float rstd = rsqrtf(var + 1e-5f);
#pragma unroll
    for (int i = 0; i < 4; i++) {
        int c = tid + i * 128;
        float y = (v[i] - mu) * rstd * g[c] + beta[c];
        out[off + c] = y;
        if (H16) oh[off + c] = __float2half(y);
    }
}

// ---------------- launch ---------------------------------------------------
extern "C" void kernel_launch(void* const* d_in, const int* in_sizes, int n_in,
                              void* d_out, int out_size)
{
    (void)in_sizes; (void)n_in; (void)out_size;
    const float* x    = (const float*)d_in[0];
    const int*   mask = (const int*)  d_in[1];
    const float* Wq = (const float*)d_in[2];
    const float* bq = (const float*)d_in[3];
    const float* Wk = (const float*)d_in[4];
    const float* bk = (const float*)d_in[5];
    const float* Wv = (const float*)d_in[6];
    const float* bv = (const float*)d_in[7];
    const float* Wo = (const float*)d_in[8];
    const float* bo = (const float*)d_in[9];
    const float* W1 = (const float*)d_in[10];
    const float* b1 = (const float*)d_in[11];
    const float* W2 = (const float*)d_in[12];
    const float* b2 = (const float*)d_in[13];
    const float* g1 = (const float*)d_in[14];
    const float* be1= (const float*)d_in[15];
    const float* g2 = (const float*)d_in[16];
    const float* be2= (const float*)d_in[17];
    float* out = (float*)d_out;

    float *x1, *tmp;
    __half *wt, *xh, *qh, *kh, *vh, *ctx, *x1h, *ffh;
    cudaGetSymbolAddress((void**)&x1,  g_x1);
    cudaGetSymbolAddress((void**)&tmp, g_tmp);
    cudaGetSymbolAddress((void**)&wt,  g_wt);
    cudaGetSymbolAddress((void**)&xh,  g_xh);
    cudaGetSymbolAddress((void**)&qh,  g_qh);
    cudaGetSymbolAddress((void**)&kh,  g_kh);
    cudaGetSymbolAddress((void**)&vh,  g_vh);
    cudaGetSymbolAddress((void**)&ctx, g_ctx);
    cudaGetSymbolAddress((void**)&x1h, g_x1h);
    cudaGetSymbolAddress((void**)&ffh, g_ffh);

    cudaFuncSetAttribute(sgemm_mma_kernel<0>,
                         cudaFuncAttributeMaxDynamicSharedMemorySize, GEMM_SMEM);
    cudaFuncSetAttribute(sgemm_mma_kernel<1>,
                         cudaFuncAttributeMaxDynamicSharedMemorySize, GEMM_SMEM);
    cudaFuncSetAttribute(sgemm_mma_kernel<2>,
                         cudaFuncAttributeMaxDynamicSharedMemorySize, GEMM_SMEM);
    cudaFuncSetAttribute(attn_mma_kernel,
                         cudaFuncAttributeMaxDynamicSharedMemorySize, ATT_SMEM);

    const int M = NTOK;

    // fused prep: all weight transposes + x convert (one launch)
    prep_kernel<<<5120, 256>>>(Wq, Wk, Wv, Wo, W1, W2, x, wt, xh);

    // fused QKV projection (fp16 out, Q pre-scaled)
    {
        dim3 grid(1536 / 128, M / 128);
        sgemm_mma_kernel<2><<<grid, 256, GEMM_SMEM>>>(
            xh, wt + OFF_WQKV, bq, bk, bv, nullptr,
            nullptr, nullptr, qh, kh, vh, M, 1536, 512);
    }

    // flash attention (fp16 tensor cores)
    {
        dim3 grid(SEQ / 128, N_HEADS, BATCH);
        attn_mma_kernel<<<grid, 256, ATT_SMEM>>>(qh, kh, vh, mask, ctx);
    }

    // Wo projection (+bias +residual x) -> tmp; x1 = LN(tmp)
    {
        dim3 grid(512 / 128, M / 128);
        sgemm_mma_kernel<0><<<grid, 256, GEMM_SMEM>>>(
            ctx, wt + OFF_WO, bo, nullptr, nullptr, x,
            tmp, nullptr, nullptr, nullptr, nullptr, M, 512, 512);
        ln_kernel<true><<<M, 128>>>(tmp, g1, be1, x1, x1h);
    }

    // FF
    {
        dim3 grid1(2048 / 128, M / 128);
        sgemm_mma_kernel<1><<<grid1, 256, GEMM_SMEM>>>(
            x1h, wt + OFF_W1, b1, nullptr, nullptr, nullptr,
            nullptr, ffh, nullptr, nullptr, nullptr, M, 2048, 512);
        dim3 grid2(512 / 128, M / 128);
        sgemm_mma_kernel<0><<<grid2, 256, GEMM_SMEM>>>(
            ffh, wt + OFF_W2, b2, nullptr, nullptr, x1,
            tmp, nullptr, nullptr, nullptr, nullptr, M, 512, 2048);
        ln_kernel<false><<<M, 128>>>(tmp, g2, be2, out, nullptr);
    }
}